// round 4
// baseline (speedup 1.0000x reference)
#include <cuda_runtime.h>
#include <math.h>

// Problem constants (fixed shapes per reference)
#define NN 50000
#define EE 800000
#define HH 8
#define HC 256
#define SLOPE 0.2f

// ---------------- static device scratch (no allocations allowed) --------------
__device__ float g_h[NN * HC];        // projected features (x @ W) per layer
__device__ float g_o[NN * HC];        // layer output (input to next layer)
__device__ float g_als[NN * HH];      // per-node src attention logits
__device__ float g_ald[NN * HH];      // per-node dst attention logits
__device__ float g_we[HH];            // edge attention weight per head
__device__ int   g_rowptr[NN + 1];
__device__ int   g_cnt[NN];
__device__ int   g_tmp[NN];           // build cursor (init'd by scan3)
__device__ int   g_esrc[EE];          // CSR-ordered source node per edge
__device__ float g_eea[EE];           // CSR-ordered edge attr per edge
__device__ float g_easum[NN];         // sum of incoming edge attr per node
__device__ int   g_bsum[64];

// ---------------- helpers ------------------------------------------------------
__device__ __forceinline__ float to_tf32(float x) {
    unsigned r;
    asm("cvt.rn.tf32.f32 %0,%1;" : "=r"(r) : "f"(x));
    return __uint_as_float(r);
}
__device__ __forceinline__ void mma_tf32(float* c, const unsigned* a, const unsigned* b) {
    asm volatile(
        "mma.sync.aligned.m16n8k8.row.col.f32.tf32.tf32.f32 "
        "{%0,%1,%2,%3},{%4,%5,%6,%7},{%8,%9},{%0,%1,%2,%3};"
        : "+f"(c[0]), "+f"(c[1]), "+f"(c[2]), "+f"(c[3])
        : "r"(a[0]), "r"(a[1]), "r"(a[2]), "r"(a[3]), "r"(b[0]), "r"(b[1]));
}
__device__ __forceinline__ float lrelu(float v) {
    return (v > 0.0f) ? v : SLOPE * v;
}

// ---------------- fused: layer-1 node logits + g_we + counter init -------------
// Blocks [0, NA1BLK): per-block recompute folds vs/vd from W1/as/ad, then
//   compute g_als/g_ald for 32 nodes (256 (n,h) pairs).
// Blocks [NA1BLK, NA1BLK+INITBLK): zero g_cnt, g_easum.
#define NA1BLK 1563
#define INITBLK 196
__global__ void __launch_bounds__(256) k_nodeatt1f(
    const float* __restrict__ x, const float* __restrict__ W1,
    const float* __restrict__ as_, const float* __restrict__ ad_,
    const float* __restrict__ We, const float* __restrict__ ae) {
    int b = blockIdx.x;
    int t = threadIdx.x;
    if (b >= NA1BLK) {
        int i = (b - NA1BLK) * 256 + t;
        if (i < NN) { g_cnt[i] = 0; g_easum[i] = 0.0f; }
        return;
    }
    __shared__ float svs[4][8], svd[4][8];
    int h = t >> 5, lane = t & 31;
    {
        float asv = as_[t], adv = ad_[t];
#pragma unroll
        for (int k = 0; k < 4; k++) {
            float w = W1[k * 256 + t];
            float s = w * asv, d = w * adv;
            for (int o = 16; o > 0; o >>= 1) {
                s += __shfl_xor_sync(0xffffffffu, s, o);
                d += __shfl_xor_sync(0xffffffffu, d, o);
            }
            if (lane == 0) { svs[k][h] = s; svd[k][h] = d; }
        }
        if (b == 0) {
            float v = We[t] * ae[t];
            for (int o = 16; o > 0; o >>= 1) v += __shfl_xor_sync(0xffffffffu, v, o);
            if (lane == 0) g_we[h] = v;
        }
    }
    __syncthreads();
    int idx = b * 256 + t;
    if (idx >= NN * 8) return;
    int n = idx >> 3, hh = idx & 7;
    float x0 = x[n * 4], x1 = x[n * 4 + 1], x2 = x[n * 4 + 2], x3 = x[n * 4 + 3];
    g_als[idx] = x0 * svs[0][hh] + x1 * svs[1][hh] + x2 * svs[2][hh] + x3 * svs[3][hh];
    g_ald[idx] = x0 * svd[0][hh] + x1 * svd[1][hh] + x2 * svd[2][hh] + x3 * svd[3][hh];
}

// ---------------- CSR build ---------------------------------------------------
__global__ void k_hist(const int* __restrict__ ei, const float* __restrict__ ea) {
    int e = blockIdx.x * blockDim.x + threadIdx.x;
    if (e < EE) {
        int d = ei[EE + e];
        atomicAdd(&g_cnt[d], 1);
        atomicAdd(&g_easum[d], ea[e]);
    }
}

__global__ void k_scan1() {
    __shared__ int s[1024];
    int tid = threadIdx.x;
    int i = blockIdx.x * 1024 + tid;
    int v = (i < NN) ? g_cnt[i] : 0;
    s[tid] = v;
    __syncthreads();
    for (int off = 1; off < 1024; off <<= 1) {
        int t = (tid >= off) ? s[tid - off] : 0;
        __syncthreads();
        s[tid] += t;
        __syncthreads();
    }
    if (i < NN) g_rowptr[i] = s[tid] - v;   // exclusive within block
    if (tid == 1023) g_bsum[blockIdx.x] = s[1023];   // block total
}

// scan3 absorbs the cross-block prefix; also writes cursor copy to g_tmp
__global__ void k_scan3() {
    __shared__ int s_off;
    int bid = blockIdx.x;
    int t = threadIdx.x;
    if (t < 32) {
        int v = 0;
        for (int b = t; b < bid; b += 32) v += g_bsum[b];
        for (int o = 16; o > 0; o >>= 1) v += __shfl_xor_sync(0xffffffffu, v, o);
        if (t == 0) s_off = v;
    }
    if (bid == 0 && t == 0) g_rowptr[NN] = EE;
    __syncthreads();
    int i = bid * 1024 + t;
    if (i < NN) {
        int r = g_rowptr[i] + s_off;
        g_rowptr[i] = r;
        g_tmp[i] = r;          // running cursor for k_build
    }
}

__global__ void k_build(const int* __restrict__ ei, const float* __restrict__ ea) {
    int e = blockIdx.x * blockDim.x + threadIdx.x;
    if (e < EE) {
        int d = ei[EE + e];
        int pos = atomicAdd(&g_tmp[d], 1);
        g_esrc[pos] = ei[e];
        g_eea[pos] = ea[e];
    }
}

// ---------------- layer-1 fused attention (rank-4 aggregation) ----------------
__global__ void __launch_bounds__(256) k_attn1(
    const float* __restrict__ x, const float* __restrict__ W1,
    const float* __restrict__ bias) {
    int warp = (blockIdx.x * blockDim.x + threadIdx.x) >> 5;
    if (warp >= NN) return;
    int n = warp;
    int l = threadIdx.x & 31;
    int head = l >> 2, c = l & 3;

    float we = g_we[head];
    float ald = g_ald[n * 8 + head];
    int start = g_rowptr[n], end = g_rowptr[n + 1];

    float m = -INFINITY, psum = 0.0f, acc = 0.0f;
    int i = start;
    for (; i + 4 <= end; i += 4) {
        int s0 = g_esrc[i], s1 = g_esrc[i + 1], s2 = g_esrc[i + 2], s3 = g_esrc[i + 3];
        float e0 = g_eea[i], e1 = g_eea[i + 1], e2 = g_eea[i + 2], e3 = g_eea[i + 3];
        float al0 = g_als[s0 * 8 + head], al1 = g_als[s1 * 8 + head];
        float al2 = g_als[s2 * 8 + head], al3 = g_als[s3 * 8 + head];
        float xv0 = x[s0 * 4 + c], xv1 = x[s1 * 4 + c];
        float xv2 = x[s2 * 4 + c], xv3 = x[s3 * 4 + c];
        float lg0 = lrelu(al0 + ald + e0 * we);
        float lg1 = lrelu(al1 + ald + e1 * we);
        float lg2 = lrelu(al2 + ald + e2 * we);
        float lg3 = lrelu(al3 + ald + e3 * we);
        float nm = fmaxf(fmaxf(m, fmaxf(lg0, lg1)), fmaxf(lg2, lg3));
        float sc = __expf(m - nm);
        float p0 = __expf(lg0 - nm), p1 = __expf(lg1 - nm);
        float p2 = __expf(lg2 - nm), p3 = __expf(lg3 - nm);
        psum = psum * sc + (p0 + p1) + (p2 + p3);
        acc = acc * sc + (p0 * xv0 + p1 * xv1) + (p2 * xv2 + p3 * xv3);
        m = nm;
    }
    for (; i < end; i++) {
        int s0 = g_esrc[i];
        float e0 = g_eea[i];
        float lg0 = lrelu(g_als[s0 * 8 + head] + ald + e0 * we);
        float nm = fmaxf(m, lg0);
        float sc = __expf(m - nm);
        float p0 = __expf(lg0 - nm);
        psum = psum * sc + p0;
        acc = acc * sc + p0 * x[s0 * 4 + c];
        m = nm;
    }

    float inv = 1.0f / (psum + 1e-16f);
    float aggv = acc * inv;
    int base = l & ~3;
    float a0 = __shfl_sync(0xffffffffu, aggv, base);
    float a1 = __shfl_sync(0xffffffffu, aggv, base + 1);
    float a2 = __shfl_sync(0xffffffffu, aggv, base + 2);
    float a3 = __shfl_sync(0xffffffffu, aggv, base + 3);

    float o[8];
#pragma unroll
    for (int cc = 0; cc < 8; cc++) {
        int ch = l * 8 + cc;
        float v = fmaf(a0, W1[ch],
                  fmaf(a1, W1[256 + ch],
                  fmaf(a2, W1[512 + ch],
                  fmaf(a3, W1[768 + ch], bias[ch]))));
        o[cc] = fmaxf(v, 0.0f);
    }
    *(float4*)(g_o + n * 256 + l * 8)     = make_float4(o[0], o[1], o[2], o[3]);
    *(float4*)(g_o + n * 256 + l * 8 + 4) = make_float4(o[4], o[5], o[6], o[7]);
}

// ---------------- node attention logits for layers 2,3 (warp per node) --------
__global__ void k_nodeatt(const float* __restrict__ as_, const float* __restrict__ ad_,
                          const float* __restrict__ We, const float* __restrict__ ae) {
    if (blockIdx.x == gridDim.x - 1) {
        int t = threadIdx.x;
        int h = t >> 5, lane = t & 31;
        float v = We[t] * ae[t];
        for (int o = 16; o > 0; o >>= 1) v += __shfl_xor_sync(0xffffffffu, v, o);
        if (lane == 0) g_we[h] = v;
        return;
    }
    int warp = (blockIdx.x * blockDim.x + threadIdx.x) >> 5;
    if (warp >= NN) return;
    int n = warp;
    int l = threadIdx.x & 31;
    const float4* hv = (const float4*)(g_h + n * 256 + l * 8);
    float4 a = hv[0], b = hv[1];
    const float* asp = as_ + l * 8;
    const float* adp = ad_ + l * 8;
    float s = a.x * asp[0] + a.y * asp[1] + a.z * asp[2] + a.w * asp[3]
            + b.x * asp[4] + b.y * asp[5] + b.z * asp[6] + b.w * asp[7];
    float d = a.x * adp[0] + a.y * adp[1] + a.z * adp[2] + a.w * adp[3]
            + b.x * adp[4] + b.y * adp[5] + b.z * adp[6] + b.w * adp[7];
    s += __shfl_xor_sync(0xffffffffu, s, 1);
    s += __shfl_xor_sync(0xffffffffu, s, 2);
    d += __shfl_xor_sync(0xffffffffu, d, 1);
    d += __shfl_xor_sync(0xffffffffu, d, 2);
    if ((l & 3) == 0) {
        g_als[n * 8 + (l >> 2)] = s;
        g_ald[n * 8 + (l >> 2)] = d;
    }
}

// ---------------- TF32 tensor-core GEMM: g_h = g_o @ W  ([M,256]x[256,256]) ---
__global__ void __launch_bounds__(256, 2) k_gemm_tf32(const float* __restrict__ W,
                                                      int M) {
    __shared__ float As[32][136];   // [k][row]
    __shared__ float Bs[32][136];   // [k][col]
    const float* A = g_o;
    float* C = g_h;

    int tid = threadIdx.x;
    int rowBase = blockIdx.y * 128;
    int colBase = blockIdx.x * 128;

    int wid = tid >> 5, lane = tid & 31;
    int wm = wid & 3, wn = wid >> 2;            // 4x2 warp grid
    int gid = lane >> 2, tg = lane & 3;

    int arow = tid >> 1, ak4 = (tid & 1) * 4;
    int bk = tid >> 3,  bn4 = (tid & 7) * 4;
    bool aval = (rowBase + arow) < M;
    const float* Aptr = A + (rowBase + arow) * 256 + ak4;
    const float* Wp   = W + bk * 256 + colBase + bn4;

    float acc[2][8][4];
#pragma unroll
    for (int i = 0; i < 2; i++)
#pragma unroll
        for (int j = 0; j < 8; j++)
#pragma unroll
            for (int q = 0; q < 4; q++) acc[i][j][q] = 0.0f;

    float4 ar[4], br[4];
#pragma unroll
    for (int u = 0; u < 4; u++) {
        ar[u] = aval ? *(const float4*)(Aptr + u * 8)
                     : make_float4(0.f, 0.f, 0.f, 0.f);
        br[u] = *(const float4*)(Wp + u * 32);
    }

#pragma unroll
    for (int it = 0; it < 8; it++) {
#pragma unroll
        for (int u = 0; u < 4; u++) {
            int kb = u * 8 + ak4;
            As[kb + 0][arow] = to_tf32(ar[u].x);
            As[kb + 1][arow] = to_tf32(ar[u].y);
            As[kb + 2][arow] = to_tf32(ar[u].z);
            As[kb + 3][arow] = to_tf32(ar[u].w);
            float4 bv = br[u];
            bv.x = to_tf32(bv.x); bv.y = to_tf32(bv.y);
            bv.z = to_tf32(bv.z); bv.w = to_tf32(bv.w);
            *(float4*)&Bs[bk][u * 32 + bn4] = bv;
        }
        __syncthreads();
        if (it < 7) {
            const float* Ap2 = Aptr + (it + 1) * 32;
            const float* Wp2 = Wp + (it + 1) * 32 * 256;
#pragma unroll
            for (int u = 0; u < 4; u++) {
                ar[u] = aval ? *(const float4*)(Ap2 + u * 8)
                             : make_float4(0.f, 0.f, 0.f, 0.f);
                br[u] = *(const float4*)(Wp2 + u * 32);
            }
        }
#pragma unroll
        for (int kt = 0; kt < 4; kt++) {
            int k0 = kt * 8 + tg;
            unsigned a[2][4];
#pragma unroll
            for (int i = 0; i < 2; i++) {
                int rb = wm * 32 + i * 16 + gid;
                a[i][0] = __float_as_uint(As[k0][rb]);
                a[i][1] = __float_as_uint(As[k0][rb + 8]);
                a[i][2] = __float_as_uint(As[k0 + 4][rb]);
                a[i][3] = __float_as_uint(As[k0 + 4][rb + 8]);
            }
            unsigned b[8][2];
#pragma unroll
            for (int j = 0; j < 8; j++) {
                int cb = wn * 64 + j * 8 + gid;
                b[j][0] = __float_as_uint(Bs[k0][cb]);
                b[j][1] = __float_as_uint(Bs[k0 + 4][cb]);
            }
#pragma unroll
            for (int i = 0; i < 2; i++)
#pragma unroll
                for (int j = 0; j < 8; j++) mma_tf32(acc[i][j], a[i], b[j]);
        }
        __syncthreads();
    }

#pragma unroll
    for (int i = 0; i < 2; i++) {
        int r0 = rowBase + wm * 32 + i * 16 + gid;
        int r1 = r0 + 8;
#pragma unroll
        for (int j = 0; j < 8; j++) {
            int col = colBase + wn * 64 + j * 8 + tg * 2;
            if (r0 < M) *(float2*)(C + r0 * 256 + col) = make_float2(acc[i][j][0], acc[i][j][1]);
            if (r1 < M) *(float2*)(C + r1 * 256 + col) = make_float2(acc[i][j][2], acc[i][j][3]);
        }
    }
}

// ---------------- fused attention + aggregation (layers 2,3, self-loops) ------
// One warp per dst node, online softmax, 4-edge unrolled single pass.
__global__ void __launch_bounds__(256) k_attn(const float* __restrict__ bias,
                                              float* __restrict__ outp) {
    int warp = (blockIdx.x * blockDim.x + threadIdx.x) >> 5;
    if (warp >= NN) return;
    int n = warp;
    int l = threadIdx.x & 31;
    int head = l >> 2;

    float we = g_we[head];
    float ald = g_ald[n * 8 + head];
    int start = g_rowptr[n], end = g_rowptr[n + 1];

    // self-loop init (fill_value='mean')
    float le = g_easum[n] / fmaxf((float)(end - start), 1.0f);
    float m = lrelu(g_als[n * 8 + head] + ald + le * we);
    float psum = 1.0f;
    float acc[8];
    {
        const float4* hv = (const float4*)(g_h + n * 256 + l * 8);
        float4 a = hv[0], b = hv[1];
        acc[0] = a.x; acc[1] = a.y; acc[2] = a.z; acc[3] = a.w;
        acc[4] = b.x; acc[5] = b.y; acc[6] = b.z; acc[7] = b.w;
    }

    int i = start;
    for (; i + 4 <= end; i += 4) {
        int s0 = g_esrc[i], s1 = g_esrc[i + 1], s2 = g_esrc[i + 2], s3 = g_esrc[i + 3];
        float e0 = g_eea[i], e1 = g_eea[i + 1], e2 = g_eea[i + 2], e3 = g_eea[i + 3];
        float al0 = g_als[s0 * 8 + head], al1 = g_als[s1 * 8 + head];
        float al2 = g_als[s2 * 8 + head], al3 = g_als[s3 * 8 + head];
        const float4* h0 = (const float4*)(g_h + s0 * 256 + l * 8);
        const float4* h1 = (const float4*)(g_h + s1 * 256 + l * 8);
        const float4* h2 = (const float4*)(g_h + s2 * 256 + l * 8);
        const float4* h3 = (const float4*)(g_h + s3 * 256 + l * 8);
        float4 a0 = h0[0], b0 = h0[1];
        float4 a1 = h1[0], b1 = h1[1];
        float4 a2 = h2[0], b2 = h2[1];
        float4 a3 = h3[0], b3 = h3[1];
        float lg0 = lrelu(al0 + ald + e0 * we);
        float lg1 = lrelu(al1 + ald + e1 * we);
        float lg2 = lrelu(al2 + ald + e2 * we);
        float lg3 = lrelu(al3 + ald + e3 * we);
        float nm = fmaxf(fmaxf(m, fmaxf(lg0, lg1)), fmaxf(lg2, lg3));
        float sc = __expf(m - nm);
        float p0 = __expf(lg0 - nm), p1 = __expf(lg1 - nm);
        float p2 = __expf(lg2 - nm), p3 = __expf(lg3 - nm);
        psum = psum * sc + (p0 + p1) + (p2 + p3);
        acc[0] = acc[0] * sc + (p0 * a0.x + p1 * a1.x) + (p2 * a2.x + p3 * a3.x);
        acc[1] = acc[1] * sc + (p0 * a0.y + p1 * a1.y) + (p2 * a2.y + p3 * a3.y);
        acc[2] = acc[2] * sc + (p0 * a0.z + p1 * a1.z) + (p2 * a2.z + p3 * a3.z);
        acc[3] = acc[3] * sc + (p0 * a0.w + p1 * a1.w) + (p2 * a2.w + p3 * a3.w);
        acc[4] = acc[4] * sc + (p0 * b0.x + p1 * b1.x) + (p2 * b2.x + p3 * b3.x);
        acc[5] = acc[5] * sc + (p0 * b0.y + p1 * b1.y) + (p2 * b2.y + p3 * b3.y);
        acc[6] = acc[6] * sc + (p0 * b0.z + p1 * b1.z) + (p2 * b2.z + p3 * b3.z);
        acc[7] = acc[7] * sc + (p0 * b0.w + p1 * b1.w) + (p2 * b2.w + p3 * b3.w);
        m = nm;
    }
    for (; i < end; i++) {
        int s0 = g_esrc[i];
        float e0 = g_eea[i];
        float lg0 = lrelu(g_als[s0 * 8 + head] + ald + e0 * we);
        const float4* h0 = (const float4*)(g_h + s0 * 256 + l * 8);
        float4 a0 = h0[0], b0 = h0[1];
        float nm = fmaxf(m, lg0);
        float sc = __expf(m - nm);
        float p0 = __expf(lg0 - nm);
        psum = psum * sc + p0;
        acc[0] = acc[0] * sc + p0 * a0.x;
        acc[1] = acc[1] * sc + p0 * a0.y;
        acc[2] = acc[2] * sc + p0 * a0.z;
        acc[3] = acc[3] * sc + p0 * a0.w;
        acc[4] = acc[4] * sc + p0 * b0.x;
        acc[5] = acc[5] * sc + p0 * b0.y;
        acc[6] = acc[6] * sc + p0 * b0.z;
        acc[7] = acc[7] * sc + p0 * b0.w;
        m = nm;
    }

    float inv = 1.0f / (psum + 1e-16f);
    const float* bp = bias + l * 8;
    float4 o0 = make_float4(fmaxf(acc[0] * inv + bp[0], 0.f),
                            fmaxf(acc[1] * inv + bp[1], 0.f),
                            fmaxf(acc[2] * inv + bp[2], 0.f),
                            fmaxf(acc[3] * inv + bp[3], 0.f));
    float4 o1 = make_float4(fmaxf(acc[4] * inv + bp[4], 0.f),
                            fmaxf(acc[5] * inv + bp[5], 0.f),
                            fmaxf(acc[6] * inv + bp[6], 0.f),
                            fmaxf(acc[7] * inv + bp[7], 0.f));
    *(float4*)(outp + n * 256 + l * 8)     = o0;
    *(float4*)(outp + n * 256 + l * 8 + 4) = o1;
}

// ---------------- launch ------------------------------------------------------
extern "C" void kernel_launch(void* const* d_in, const int* in_sizes, int n_in,
                              void* d_out, int out_size) {
    const float* x   = (const float*)d_in[0];
    const int*   ei  = (const int*)d_in[1];
    const float* ea  = (const float*)d_in[2];
    const float* W1  = (const float*)d_in[3];
    const float* as1 = (const float*)d_in[4];
    const float* ad1 = (const float*)d_in[5];
    const float* We1 = (const float*)d_in[6];
    const float* ae1 = (const float*)d_in[7];
    const float* b1  = (const float*)d_in[8];
    const float* W2  = (const float*)d_in[9];
    const float* as2 = (const float*)d_in[10];
    const float* ad2 = (const float*)d_in[11];
    const float* We2 = (const float*)d_in[12];
    const float* ae2 = (const float*)d_in[13];
    const float* b2  = (const float*)d_in[14];
    const float* W3  = (const float*)d_in[15];
    const float* as3 = (const float*)d_in[16];
    const float* ad3 = (const float*)d_in[17];
    const float* We3 = (const float*)d_in[18];
    const float* ae3 = (const float*)d_in[19];
    const float* b3  = (const float*)d_in[20];
    float* out = (float*)d_out;

    const int nblkE   = (EE + 255) / 256;
    const int scanBlk = (NN + 1023) / 1024;        // 49
    const int attnBlk = (NN * 32 + 255) / 256;     // 6250

    // --- layer-1 node logits + g_we + counter init (independent of CSR) ---
    k_nodeatt1f<<<NA1BLK + INITBLK, 256>>>(x, W1, as1, ad1, We1, ae1);

    // --- CSR build ---
    k_hist<<<nblkE, 256>>>(ei, ea);
    k_scan1<<<scanBlk, 1024>>>();
    k_scan3<<<scanBlk, 1024>>>();
    k_build<<<nblkE, 256>>>(ei, ea);

    dim3 gGemm(2, (NN + 127) / 128);

    // --- layer 1 (no self loops, rank-4 fold) ---
    k_attn1<<<attnBlk, 256>>>(x, W1, b1);

    // --- layer 2 (self loops) ---
    k_gemm_tf32<<<gGemm, 256>>>(W2, NN);
    k_nodeatt<<<attnBlk + 1, 256>>>(as2, ad2, We2, ae2);
    {
        float* g_o_ptr = nullptr;
        cudaGetSymbolAddress((void**)&g_o_ptr, g_o);
        k_attn<<<attnBlk, 256>>>(b2, g_o_ptr);
    }

    // --- layer 3 (self loops) -> d_out ---
    k_gemm_tf32<<<gGemm, 256>>>(W3, NN);
    k_nodeatt<<<attnBlk + 1, 256>>>(as3, ad3, We3, ae3);
    k_attn<<<attnBlk, 256>>>(b3, out);
}

// round 5
// speedup vs baseline: 1.0140x; 1.0140x over previous
#include <cuda_runtime.h>
#include <math.h>

// Problem constants (fixed shapes per reference)
#define NN 50000
#define EE 800000
#define HH 8
#define HC 256
#define SLOPE 0.2f

// ---------------- static device scratch (no allocations allowed) --------------
__device__ float g_h[NN * HC];        // projected features (x @ W) per layer
__device__ float g_o[NN * HC];        // layer output (input to next layer)
__device__ float g_als[NN * HH];      // per-node src attention logits
__device__ float g_ald[NN * HH];      // per-node dst attention logits
__device__ float g_we[HH];            // edge attention weight per head
__device__ int   g_rowptr[NN + 1];
__device__ int   g_cnt[NN];
__device__ int   g_tmp[NN];           // build cursor (init'd by scan3)
__device__ int2  g_edge[EE];          // CSR-ordered (src, edge_attr bits)
__device__ float g_easum[NN];         // sum of incoming edge attr per node
__device__ int   g_bsum[64];

// ---------------- helpers ------------------------------------------------------
__device__ __forceinline__ float to_tf32(float x) {
    unsigned r;
    asm("cvt.rn.tf32.f32 %0,%1;" : "=r"(r) : "f"(x));
    return __uint_as_float(r);
}
__device__ __forceinline__ void mma_tf32(float* c, const unsigned* a, const unsigned* b) {
    asm volatile(
        "mma.sync.aligned.m16n8k8.row.col.f32.tf32.tf32.f32 "
        "{%0,%1,%2,%3},{%4,%5,%6,%7},{%8,%9},{%0,%1,%2,%3};"
        : "+f"(c[0]), "+f"(c[1]), "+f"(c[2]), "+f"(c[3])
        : "r"(a[0]), "r"(a[1]), "r"(a[2]), "r"(a[3]), "r"(b[0]), "r"(b[1]));
}
__device__ __forceinline__ float lrelu(float v) {
    return (v > 0.0f) ? v : SLOPE * v;
}

// ---------------- fused: layer-1 node logits + g_we + counter init -------------
#define NA1BLK 1563
#define INITBLK 196
__global__ void __launch_bounds__(256) k_nodeatt1f(
    const float* __restrict__ x, const float* __restrict__ W1,
    const float* __restrict__ as_, const float* __restrict__ ad_,
    const float* __restrict__ We, const float* __restrict__ ae) {
    int b = blockIdx.x;
    int t = threadIdx.x;
    if (b >= NA1BLK) {
        int i = (b - NA1BLK) * 256 + t;
        if (i < NN) { g_cnt[i] = 0; g_easum[i] = 0.0f; }
        return;
    }
    __shared__ float svs[4][8], svd[4][8];
    int h = t >> 5, lane = t & 31;
    {
        float asv = as_[t], adv = ad_[t];
#pragma unroll
        for (int k = 0; k < 4; k++) {
            float w = W1[k * 256 + t];
            float s = w * asv, d = w * adv;
            for (int o = 16; o > 0; o >>= 1) {
                s += __shfl_xor_sync(0xffffffffu, s, o);
                d += __shfl_xor_sync(0xffffffffu, d, o);
            }
            if (lane == 0) { svs[k][h] = s; svd[k][h] = d; }
        }
        if (b == 0) {
            float v = We[t] * ae[t];
            for (int o = 16; o > 0; o >>= 1) v += __shfl_xor_sync(0xffffffffu, v, o);
            if (lane == 0) g_we[h] = v;
        }
    }
    __syncthreads();
    int idx = b * 256 + t;
    if (idx >= NN * 8) return;
    int n = idx >> 3, hh = idx & 7;
    float x0 = x[n * 4], x1 = x[n * 4 + 1], x2 = x[n * 4 + 2], x3 = x[n * 4 + 3];
    g_als[idx] = x0 * svs[0][hh] + x1 * svs[1][hh] + x2 * svs[2][hh] + x3 * svs[3][hh];
    g_ald[idx] = x0 * svd[0][hh] + x1 * svd[1][hh] + x2 * svd[2][hh] + x3 * svd[3][hh];
}

// ---------------- CSR build ---------------------------------------------------
__global__ void k_hist(const int* __restrict__ ei, const float* __restrict__ ea) {
    int e = blockIdx.x * blockDim.x + threadIdx.x;
    if (e < EE) {
        int d = ei[EE + e];
        atomicAdd(&g_cnt[d], 1);
        atomicAdd(&g_easum[d], ea[e]);
    }
}

__global__ void k_scan1() {
    __shared__ int s[1024];
    int tid = threadIdx.x;
    int i = blockIdx.x * 1024 + tid;
    int v = (i < NN) ? g_cnt[i] : 0;
    s[tid] = v;
    __syncthreads();
    for (int off = 1; off < 1024; off <<= 1) {
        int t = (tid >= off) ? s[tid - off] : 0;
        __syncthreads();
        s[tid] += t;
        __syncthreads();
    }
    if (i < NN) g_rowptr[i] = s[tid] - v;   // exclusive within block
    if (tid == 1023) g_bsum[blockIdx.x] = s[1023];   // block total
}

// scan3 absorbs the cross-block prefix; also writes cursor copy to g_tmp
__global__ void k_scan3() {
    __shared__ int s_off;
    int bid = blockIdx.x;
    int t = threadIdx.x;
    if (t < 32) {
        int v = 0;
        for (int b = t; b < bid; b += 32) v += g_bsum[b];
        for (int o = 16; o > 0; o >>= 1) v += __shfl_xor_sync(0xffffffffu, v, o);
        if (t == 0) s_off = v;
    }
    if (bid == 0 && t == 0) g_rowptr[NN] = EE;
    __syncthreads();
    int i = bid * 1024 + t;
    if (i < NN) {
        int r = g_rowptr[i] + s_off;
        g_rowptr[i] = r;
        g_tmp[i] = r;          // running cursor for k_build
    }
}

__global__ void k_build(const int* __restrict__ ei, const float* __restrict__ ea) {
    int e = blockIdx.x * blockDim.x + threadIdx.x;
    if (e < EE) {
        int d = ei[EE + e];
        int pos = atomicAdd(&g_tmp[d], 1);
        int2 rec;
        rec.x = ei[e];
        rec.y = __float_as_int(ea[e]);
        g_edge[pos] = rec;
    }
}

// ---------------- layer-1 fused attention (rank-4 aggregation) ----------------
__global__ void __launch_bounds__(256) k_attn1(
    const float* __restrict__ x, const float* __restrict__ W1,
    const float* __restrict__ bias) {
    int warp = (blockIdx.x * blockDim.x + threadIdx.x) >> 5;
    if (warp >= NN) return;
    int n = warp;
    int l = threadIdx.x & 31;
    int head = l >> 2, c = l & 3;

    float we = g_we[head];
    float ald = g_ald[n * 8 + head];
    int start = g_rowptr[n], end = g_rowptr[n + 1];

    float m = -INFINITY, psum = 0.0f, acc = 0.0f;
    int i = start;
    for (; i + 4 <= end; i += 4) {
        int2 r0 = __ldcs(&g_edge[i]),     r1 = __ldcs(&g_edge[i + 1]);
        int2 r2 = __ldcs(&g_edge[i + 2]), r3 = __ldcs(&g_edge[i + 3]);
        int s0 = r0.x, s1 = r1.x, s2 = r2.x, s3 = r3.x;
        float e0 = __int_as_float(r0.y), e1 = __int_as_float(r1.y);
        float e2 = __int_as_float(r2.y), e3 = __int_as_float(r3.y);
        float al0 = g_als[s0 * 8 + head], al1 = g_als[s1 * 8 + head];
        float al2 = g_als[s2 * 8 + head], al3 = g_als[s3 * 8 + head];
        float xv0 = x[s0 * 4 + c], xv1 = x[s1 * 4 + c];
        float xv2 = x[s2 * 4 + c], xv3 = x[s3 * 4 + c];
        float lg0 = lrelu(al0 + ald + e0 * we);
        float lg1 = lrelu(al1 + ald + e1 * we);
        float lg2 = lrelu(al2 + ald + e2 * we);
        float lg3 = lrelu(al3 + ald + e3 * we);
        float nm = fmaxf(fmaxf(m, fmaxf(lg0, lg1)), fmaxf(lg2, lg3));
        float sc = __expf(m - nm);
        float p0 = __expf(lg0 - nm), p1 = __expf(lg1 - nm);
        float p2 = __expf(lg2 - nm), p3 = __expf(lg3 - nm);
        psum = psum * sc + (p0 + p1) + (p2 + p3);
        acc = acc * sc + (p0 * xv0 + p1 * xv1) + (p2 * xv2 + p3 * xv3);
        m = nm;
    }
    for (; i < end; i++) {
        int2 r0 = __ldcs(&g_edge[i]);
        int s0 = r0.x;
        float e0 = __int_as_float(r0.y);
        float lg0 = lrelu(g_als[s0 * 8 + head] + ald + e0 * we);
        float nm = fmaxf(m, lg0);
        float sc = __expf(m - nm);
        float p0 = __expf(lg0 - nm);
        psum = psum * sc + p0;
        acc = acc * sc + p0 * x[s0 * 4 + c];
        m = nm;
    }

    float inv = 1.0f / (psum + 1e-16f);
    float aggv = acc * inv;
    int base = l & ~3;
    float a0 = __shfl_sync(0xffffffffu, aggv, base);
    float a1 = __shfl_sync(0xffffffffu, aggv, base + 1);
    float a2 = __shfl_sync(0xffffffffu, aggv, base + 2);
    float a3 = __shfl_sync(0xffffffffu, aggv, base + 3);

    float o[8];
#pragma unroll
    for (int cc = 0; cc < 8; cc++) {
        int ch = l * 8 + cc;
        float v = fmaf(a0, W1[ch],
                  fmaf(a1, W1[256 + ch],
                  fmaf(a2, W1[512 + ch],
                  fmaf(a3, W1[768 + ch], bias[ch]))));
        o[cc] = fmaxf(v, 0.0f);
    }
    __stcs((float4*)(g_o + n * 256 + l * 8),     make_float4(o[0], o[1], o[2], o[3]));
    __stcs((float4*)(g_o + n * 256 + l * 8 + 4), make_float4(o[4], o[5], o[6], o[7]));
}

// ---------------- node attention logits for layers 2,3 (warp per node) --------
// Sequential read of g_h also pre-warms L2 for the attn gather that follows.
__global__ void k_nodeatt(const float* __restrict__ as_, const float* __restrict__ ad_,
                          const float* __restrict__ We, const float* __restrict__ ae) {
    if (blockIdx.x == gridDim.x - 1) {
        int t = threadIdx.x;
        int h = t >> 5, lane = t & 31;
        float v = We[t] * ae[t];
        for (int o = 16; o > 0; o >>= 1) v += __shfl_xor_sync(0xffffffffu, v, o);
        if (lane == 0) g_we[h] = v;
        return;
    }
    int warp = (blockIdx.x * blockDim.x + threadIdx.x) >> 5;
    if (warp >= NN) return;
    int n = warp;
    int l = threadIdx.x & 31;
    const float4* hv = (const float4*)(g_h + n * 256 + l * 8);
    float4 a = hv[0], b = hv[1];
    const float* asp = as_ + l * 8;
    const float* adp = ad_ + l * 8;
    float s = a.x * asp[0] + a.y * asp[1] + a.z * asp[2] + a.w * asp[3]
            + b.x * asp[4] + b.y * asp[5] + b.z * asp[6] + b.w * asp[7];
    float d = a.x * adp[0] + a.y * adp[1] + a.z * adp[2] + a.w * adp[3]
            + b.x * adp[4] + b.y * adp[5] + b.z * adp[6] + b.w * adp[7];
    s += __shfl_xor_sync(0xffffffffu, s, 1);
    s += __shfl_xor_sync(0xffffffffu, s, 2);
    d += __shfl_xor_sync(0xffffffffu, d, 1);
    d += __shfl_xor_sync(0xffffffffu, d, 2);
    if ((l & 3) == 0) {
        g_als[n * 8 + (l >> 2)] = s;
        g_ald[n * 8 + (l >> 2)] = d;
    }
}

// ---------------- TF32 tensor-core GEMM: g_h = g_o @ W  ([M,256]x[256,256]) ---
__global__ void __launch_bounds__(256, 2) k_gemm_tf32(const float* __restrict__ W,
                                                      int M) {
    __shared__ float As[32][136];   // [k][row]
    __shared__ float Bs[32][136];   // [k][col]
    const float* A = g_o;
    float* C = g_h;

    int tid = threadIdx.x;
    int rowBase = blockIdx.y * 128;
    int colBase = blockIdx.x * 128;

    int wid = tid >> 5, lane = tid & 31;
    int wm = wid & 3, wn = wid >> 2;            // 4x2 warp grid
    int gid = lane >> 2, tg = lane & 3;

    int arow = tid >> 1, ak4 = (tid & 1) * 4;
    int bk = tid >> 3,  bn4 = (tid & 7) * 4;
    bool aval = (rowBase + arow) < M;
    const float* Aptr = A + (rowBase + arow) * 256 + ak4;
    const float* Wp   = W + bk * 256 + colBase + bn4;

    float acc[2][8][4];
#pragma unroll
    for (int i = 0; i < 2; i++)
#pragma unroll
        for (int j = 0; j < 8; j++)
#pragma unroll
            for (int q = 0; q < 4; q++) acc[i][j][q] = 0.0f;

    float4 ar[4], br[4];
#pragma unroll
    for (int u = 0; u < 4; u++) {
        ar[u] = aval ? *(const float4*)(Aptr + u * 8)
                     : make_float4(0.f, 0.f, 0.f, 0.f);
        br[u] = *(const float4*)(Wp + u * 32);
    }

#pragma unroll
    for (int it = 0; it < 8; it++) {
#pragma unroll
        for (int u = 0; u < 4; u++) {
            int kb = u * 8 + ak4;
            As[kb + 0][arow] = to_tf32(ar[u].x);
            As[kb + 1][arow] = to_tf32(ar[u].y);
            As[kb + 2][arow] = to_tf32(ar[u].z);
            As[kb + 3][arow] = to_tf32(ar[u].w);
            float4 bv = br[u];
            bv.x = to_tf32(bv.x); bv.y = to_tf32(bv.y);
            bv.z = to_tf32(bv.z); bv.w = to_tf32(bv.w);
            *(float4*)&Bs[bk][u * 32 + bn4] = bv;
        }
        __syncthreads();
        if (it < 7) {
            const float* Ap2 = Aptr + (it + 1) * 32;
            const float* Wp2 = Wp + (it + 1) * 32 * 256;
#pragma unroll
            for (int u = 0; u < 4; u++) {
                ar[u] = aval ? *(const float4*)(Ap2 + u * 8)
                             : make_float4(0.f, 0.f, 0.f, 0.f);
                br[u] = *(const float4*)(Wp2 + u * 32);
            }
        }
#pragma unroll
        for (int kt = 0; kt < 4; kt++) {
            int k0 = kt * 8 + tg;
            unsigned a[2][4];
#pragma unroll
            for (int i = 0; i < 2; i++) {
                int rb = wm * 32 + i * 16 + gid;
                a[i][0] = __float_as_uint(As[k0][rb]);
                a[i][1] = __float_as_uint(As[k0][rb + 8]);
                a[i][2] = __float_as_uint(As[k0 + 4][rb]);
                a[i][3] = __float_as_uint(As[k0 + 4][rb + 8]);
            }
            unsigned b[8][2];
#pragma unroll
            for (int j = 0; j < 8; j++) {
                int cb = wn * 64 + j * 8 + gid;
                b[j][0] = __float_as_uint(Bs[k0][cb]);
                b[j][1] = __float_as_uint(Bs[k0 + 4][cb]);
            }
#pragma unroll
            for (int i = 0; i < 2; i++)
#pragma unroll
                for (int j = 0; j < 8; j++) mma_tf32(acc[i][j], a[i], b[j]);
        }
        __syncthreads();
    }

#pragma unroll
    for (int i = 0; i < 2; i++) {
        int r0 = rowBase + wm * 32 + i * 16 + gid;
        int r1 = r0 + 8;
#pragma unroll
        for (int j = 0; j < 8; j++) {
            int col = colBase + wn * 64 + j * 8 + tg * 2;
            if (r0 < M) *(float2*)(C + r0 * 256 + col) = make_float2(acc[i][j][0], acc[i][j][1]);
            if (r1 < M) *(float2*)(C + r1 * 256 + col) = make_float2(acc[i][j][2], acc[i][j][3]);
        }
    }
}

// ---------------- fused attention + aggregation (layers 2,3, self-loops) ------
// One warp per dst node, online softmax, unroll-2 (R3-proven config).
// Streaming data (edge records, outputs) uses evict-first to keep g_h resident.
__global__ void __launch_bounds__(256) k_attn(const float* __restrict__ bias,
                                              float* __restrict__ outp) {
    int warp = (blockIdx.x * blockDim.x + threadIdx.x) >> 5;
    if (warp >= NN) return;
    int n = warp;
    int l = threadIdx.x & 31;
    int head = l >> 2;

    float we = g_we[head];
    float ald = g_ald[n * 8 + head];
    int start = g_rowptr[n], end = g_rowptr[n + 1];

    // self-loop init (fill_value='mean')
    float le = g_easum[n] / fmaxf((float)(end - start), 1.0f);
    float m = lrelu(g_als[n * 8 + head] + ald + le * we);
    float psum = 1.0f;
    float acc[8];
    {
        const float4* hv = (const float4*)(g_h + n * 256 + l * 8);
        float4 a = hv[0], b = hv[1];
        acc[0] = a.x; acc[1] = a.y; acc[2] = a.z; acc[3] = a.w;
        acc[4] = b.x; acc[5] = b.y; acc[6] = b.z; acc[7] = b.w;
    }

    int i = start;
    for (; i + 2 <= end; i += 2) {
        int2 r0 = __ldcs(&g_edge[i]), r1 = __ldcs(&g_edge[i + 1]);
        int s0 = r0.x, s1 = r1.x;
        float e0 = __int_as_float(r0.y), e1 = __int_as_float(r1.y);
        float al0 = g_als[s0 * 8 + head], al1 = g_als[s1 * 8 + head];
        const float4* h0 = (const float4*)(g_h + s0 * 256 + l * 8);
        const float4* h1 = (const float4*)(g_h + s1 * 256 + l * 8);
        float4 a0 = h0[0], b0 = h0[1];
        float4 a1 = h1[0], b1 = h1[1];
        float lg0 = lrelu(al0 + ald + e0 * we);
        float lg1 = lrelu(al1 + ald + e1 * we);
        float nm = fmaxf(m, fmaxf(lg0, lg1));
        float sc = __expf(m - nm);
        float p0 = __expf(lg0 - nm);
        float p1 = __expf(lg1 - nm);
        psum = psum * sc + p0 + p1;
        acc[0] = acc[0] * sc + p0 * a0.x + p1 * a1.x;
        acc[1] = acc[1] * sc + p0 * a0.y + p1 * a1.y;
        acc[2] = acc[2] * sc + p0 * a0.z + p1 * a1.z;
        acc[3] = acc[3] * sc + p0 * a0.w + p1 * a1.w;
        acc[4] = acc[4] * sc + p0 * b0.x + p1 * b1.x;
        acc[5] = acc[5] * sc + p0 * b0.y + p1 * b1.y;
        acc[6] = acc[6] * sc + p0 * b0.z + p1 * b1.z;
        acc[7] = acc[7] * sc + p0 * b0.w + p1 * b1.w;
        m = nm;
    }
    if (i < end) {
        int2 r0 = __ldcs(&g_edge[i]);
        int s0 = r0.x;
        float e0 = __int_as_float(r0.y);
        float lg0 = lrelu(g_als[s0 * 8 + head] + ald + e0 * we);
        const float4* h0 = (const float4*)(g_h + s0 * 256 + l * 8);
        float4 a0 = h0[0], b0 = h0[1];
        float nm = fmaxf(m, lg0);
        float sc = __expf(m - nm);
        float p0 = __expf(lg0 - nm);
        psum = psum * sc + p0;
        acc[0] = acc[0] * sc + p0 * a0.x;
        acc[1] = acc[1] * sc + p0 * a0.y;
        acc[2] = acc[2] * sc + p0 * a0.z;
        acc[3] = acc[3] * sc + p0 * a0.w;
        acc[4] = acc[4] * sc + p0 * b0.x;
        acc[5] = acc[5] * sc + p0 * b0.y;
        acc[6] = acc[6] * sc + p0 * b0.z;
        acc[7] = acc[7] * sc + p0 * b0.w;
    }

    float inv = 1.0f / (psum + 1e-16f);
    const float* bp = bias + l * 8;
    float4 o0 = make_float4(fmaxf(acc[0] * inv + bp[0], 0.f),
                            fmaxf(acc[1] * inv + bp[1], 0.f),
                            fmaxf(acc[2] * inv + bp[2], 0.f),
                            fmaxf(acc[3] * inv + bp[3], 0.f));
    float4 o1 = make_float4(fmaxf(acc[4] * inv + bp[4], 0.f),
                            fmaxf(acc[5] * inv + bp[5], 0.f),
                            fmaxf(acc[6] * inv + bp[6], 0.f),
                            fmaxf(acc[7] * inv + bp[7], 0.f));
    __stcs((float4*)(outp + n * 256 + l * 8),     o0);
    __stcs((float4*)(outp + n * 256 + l * 8 + 4), o1);
}

// ---------------- launch ------------------------------------------------------
extern "C" void kernel_launch(void* const* d_in, const int* in_sizes, int n_in,
                              void* d_out, int out_size) {
    const float* x   = (const float*)d_in[0];
    const int*   ei  = (const int*)d_in[1];
    const float* ea  = (const float*)d_in[2];
    const float* W1  = (const float*)d_in[3];
    const float* as1 = (const float*)d_in[4];
    const float* ad1 = (const float*)d_in[5];
    const float* We1 = (const float*)d_in[6];
    const float* ae1 = (const float*)d_in[7];
    const float* b1  = (const float*)d_in[8];
    const float* W2  = (const float*)d_in[9];
    const float* as2 = (const float*)d_in[10];
    const float* ad2 = (const float*)d_in[11];
    const float* We2 = (const float*)d_in[12];
    const float* ae2 = (const float*)d_in[13];
    const float* b2  = (const float*)d_in[14];
    const float* W3  = (const float*)d_in[15];
    const float* as3 = (const float*)d_in[16];
    const float* ad3 = (const float*)d_in[17];
    const float* We3 = (const float*)d_in[18];
    const float* ae3 = (const float*)d_in[19];
    const float* b3  = (const float*)d_in[20];
    float* out = (float*)d_out;

    const int nblkE   = (EE + 255) / 256;
    const int scanBlk = (NN + 1023) / 1024;        // 49
    const int attnBlk = (NN * 32 + 255) / 256;     // 6250

    // --- layer-1 node logits + g_we + counter init (independent of CSR) ---
    k_nodeatt1f<<<NA1BLK + INITBLK, 256>>>(x, W1, as1, ad1, We1, ae1);

    // --- CSR build ---
    k_hist<<<nblkE, 256>>>(ei, ea);
    k_scan1<<<scanBlk, 1024>>>();
    k_scan3<<<scanBlk, 1024>>>();
    k_build<<<nblkE, 256>>>(ei, ea);

    dim3 gGemm(2, (NN + 127) / 128);

    // --- layer 1 (no self loops, rank-4 fold) ---
    k_attn1<<<attnBlk, 256>>>(x, W1, b1);

    // --- layer 2 (self loops) ---
    k_gemm_tf32<<<gGemm, 256>>>(W2, NN);
    k_nodeatt<<<attnBlk + 1, 256>>>(as2, ad2, We2, ae2);
    {
        float* g_o_ptr = nullptr;
        cudaGetSymbolAddress((void**)&g_o_ptr, g_o);
        k_attn<<<attnBlk, 256>>>(b2, g_o_ptr);
    }

    // --- layer 3 (self loops) -> d_out ---
    k_gemm_tf32<<<gGemm, 256>>>(W3, NN);
    k_nodeatt<<<attnBlk + 1, 256>>>(as3, ad3, We3, ae3);
    k_attn<<<attnBlk, 256>>>(b3, out);
}

// round 6
// speedup vs baseline: 1.1079x; 1.0926x over previous
#include <cuda_runtime.h>
#include <cuda_fp16.h>
#include <math.h>

// Problem constants (fixed shapes per reference)
#define NN 50000
#define EE 800000
#define HH 8
#define HC 256
#define SLOPE 0.2f

// ---------------- static device scratch (no allocations allowed) --------------
__device__ __half2 g_h2[NN * HC / 2]; // projected features (fp16, 128 half2/row)
__device__ float g_o[NN * HC];        // layer output (input to next layer, fp32)
__device__ float g_als[NN * HH];      // per-node src attention logits
__device__ float g_ald[NN * HH];      // per-node dst attention logits
__device__ float g_we[HH];            // edge attention weight per head
__device__ int   g_rowptr[NN + 1];
__device__ int   g_cnt[NN];           // zeroed by previous launch's tail (or static init)
__device__ int   g_tmp[NN];           // build cursor (init'd by scan)
__device__ int2  g_edge[EE];          // CSR-ordered (src, edge_attr bits)
__device__ float g_easum[NN];         // sum of incoming edge attr per node
__device__ int   g_bsum[64];
__device__ int   g_bflag[64];         // scan lookback flags (reset by attn tail)

// ---------------- helpers ------------------------------------------------------
__device__ __forceinline__ float to_tf32(float x) {
    unsigned r;
    asm("cvt.rn.tf32.f32 %0,%1;" : "=r"(r) : "f"(x));
    return __uint_as_float(r);
}
__device__ __forceinline__ void mma_tf32(float* c, const unsigned* a, const unsigned* b) {
    asm volatile(
        "mma.sync.aligned.m16n8k8.row.col.f32.tf32.tf32.f32 "
        "{%0,%1,%2,%3},{%4,%5,%6,%7},{%8,%9},{%0,%1,%2,%3};"
        : "+f"(c[0]), "+f"(c[1]), "+f"(c[2]), "+f"(c[3])
        : "r"(a[0]), "r"(a[1]), "r"(a[2]), "r"(a[3]), "r"(b[0]), "r"(b[1]));
}
__device__ __forceinline__ float lrelu(float v) {
    return (v > 0.0f) ? v : SLOPE * v;
}
// unpack uint4 (8 fp16) -> 8 floats
__device__ __forceinline__ void unp8(uint4 v, float* f) {
    float2 c0 = __half22float2(*(__half2*)&v.x);
    float2 c1 = __half22float2(*(__half2*)&v.y);
    float2 c2 = __half22float2(*(__half2*)&v.z);
    float2 c3 = __half22float2(*(__half2*)&v.w);
    f[0] = c0.x; f[1] = c0.y; f[2] = c1.x; f[3] = c1.y;
    f[4] = c2.x; f[5] = c2.y; f[6] = c3.x; f[7] = c3.y;
}

// ---------------- front kernel: layer-1 node logits + g_we + histogram --------
// Blocks [0, NA1BLK): layer-1 folded logits (recompute 4x8 folds per block).
// Blocks [NA1BLK, NA1BLK+HISTBLK): edge histogram (g_cnt zeroed by prev launch).
#define NA1BLK 1563
#define HISTBLK 3125
__global__ void __launch_bounds__(256) k_front(
    const float* __restrict__ x, const float* __restrict__ W1,
    const float* __restrict__ as_, const float* __restrict__ ad_,
    const float* __restrict__ We, const float* __restrict__ ae,
    const int* __restrict__ ei, const float* __restrict__ ea) {
    int b = blockIdx.x;
    int t = threadIdx.x;
    if (b >= NA1BLK) {
        int e = (b - NA1BLK) * 256 + t;
        if (e < EE) {
            int d = ei[EE + e];
            atomicAdd(&g_cnt[d], 1);
            atomicAdd(&g_easum[d], ea[e]);
        }
        return;
    }
    __shared__ float svs[4][8], svd[4][8];
    int h = t >> 5, lane = t & 31;
    {
        float asv = as_[t], adv = ad_[t];
#pragma unroll
        for (int k = 0; k < 4; k++) {
            float w = W1[k * 256 + t];
            float s = w * asv, d = w * adv;
            for (int o = 16; o > 0; o >>= 1) {
                s += __shfl_xor_sync(0xffffffffu, s, o);
                d += __shfl_xor_sync(0xffffffffu, d, o);
            }
            if (lane == 0) { svs[k][h] = s; svd[k][h] = d; }
        }
        if (b == 0) {
            float v = We[t] * ae[t];
            for (int o = 16; o > 0; o >>= 1) v += __shfl_xor_sync(0xffffffffu, v, o);
            if (lane == 0) g_we[h] = v;
        }
    }
    __syncthreads();
    int idx = b * 256 + t;
    if (idx >= NN * 8) return;
    int n = idx >> 3, hh = idx & 7;
    float x0 = x[n * 4], x1 = x[n * 4 + 1], x2 = x[n * 4 + 2], x3 = x[n * 4 + 3];
    g_als[idx] = x0 * svs[0][hh] + x1 * svs[1][hh] + x2 * svs[2][hh] + x3 * svs[3][hh];
    g_ald[idx] = x0 * svd[0][hh] + x1 * svd[1][hh] + x2 * svd[2][hh] + x3 * svd[3][hh];
}

// ---------------- single-kernel scan (decoupled lookback, 49 co-resident blocks)
__global__ void k_scan() {
    __shared__ int s[1024];
    __shared__ int s_off;
    int bid = blockIdx.x, tid = threadIdx.x;
    int i = bid * 1024 + tid;
    int v = (i < NN) ? g_cnt[i] : 0;
    s[tid] = v;
    __syncthreads();
    for (int off = 1; off < 1024; off <<= 1) {
        int t = (tid >= off) ? s[tid - off] : 0;
        __syncthreads();
        s[tid] += t;
        __syncthreads();
    }
    if (tid == 1023) {                  // publish block aggregate
        g_bsum[bid] = s[1023];
        __threadfence();
        atomicExch(&g_bflag[bid], 1);
    }
    if (tid < 32) {                     // lookback: sum predecessor aggregates
        int sum = 0;
        for (int p = tid; p < bid; p += 32) {
            while (atomicAdd(&g_bflag[p], 0) == 0) {}
            sum += atomicAdd(&g_bsum[p], 0);
        }
        for (int o = 16; o > 0; o >>= 1) sum += __shfl_xor_sync(0xffffffffu, sum, o);
        if (tid == 0) s_off = sum;
    }
    if (bid == 0 && tid == 0) g_rowptr[NN] = EE;
    __syncthreads();
    if (i < NN) {
        int r = s[tid] - v + s_off;     // exclusive prefix
        g_rowptr[i] = r;
        g_tmp[i] = r;                   // running cursor for k_build
    }
}

__global__ void k_build(const int* __restrict__ ei, const float* __restrict__ ea) {
    int e = blockIdx.x * blockDim.x + threadIdx.x;
    if (e < EE) {
        int d = ei[EE + e];
        int pos = atomicAdd(&g_tmp[d], 1);
        int2 rec;
        rec.x = ei[e];
        rec.y = __float_as_int(ea[e]);
        g_edge[pos] = rec;
    }
}

// ---------------- layer-1 fused attention (rank-4 aggregation) ----------------
__global__ void __launch_bounds__(256) k_attn1(
    const float* __restrict__ x, const float* __restrict__ W1,
    const float* __restrict__ bias) {
    int warp = (blockIdx.x * blockDim.x + threadIdx.x) >> 5;
    if (warp >= NN) return;
    int n = warp;
    int l = threadIdx.x & 31;
    int head = l >> 2, c = l & 3;

    float we = g_we[head];
    float ald = g_ald[n * 8 + head];
    int start = g_rowptr[n], end = g_rowptr[n + 1];

    float m = -INFINITY, psum = 0.0f, acc = 0.0f;
    int i = start;
    for (; i + 4 <= end; i += 4) {
        int2 r0 = __ldcs(&g_edge[i]),     r1 = __ldcs(&g_edge[i + 1]);
        int2 r2 = __ldcs(&g_edge[i + 2]), r3 = __ldcs(&g_edge[i + 3]);
        int s0 = r0.x, s1 = r1.x, s2 = r2.x, s3 = r3.x;
        float e0 = __int_as_float(r0.y), e1 = __int_as_float(r1.y);
        float e2 = __int_as_float(r2.y), e3 = __int_as_float(r3.y);
        float al0 = g_als[s0 * 8 + head], al1 = g_als[s1 * 8 + head];
        float al2 = g_als[s2 * 8 + head], al3 = g_als[s3 * 8 + head];
        float xv0 = x[s0 * 4 + c], xv1 = x[s1 * 4 + c];
        float xv2 = x[s2 * 4 + c], xv3 = x[s3 * 4 + c];
        float lg0 = lrelu(al0 + ald + e0 * we);
        float lg1 = lrelu(al1 + ald + e1 * we);
        float lg2 = lrelu(al2 + ald + e2 * we);
        float lg3 = lrelu(al3 + ald + e3 * we);
        float nm = fmaxf(fmaxf(m, fmaxf(lg0, lg1)), fmaxf(lg2, lg3));
        float sc = __expf(m - nm);
        float p0 = __expf(lg0 - nm), p1 = __expf(lg1 - nm);
        float p2 = __expf(lg2 - nm), p3 = __expf(lg3 - nm);
        psum = psum * sc + (p0 + p1) + (p2 + p3);
        acc = acc * sc + (p0 * xv0 + p1 * xv1) + (p2 * xv2 + p3 * xv3);
        m = nm;
    }
    for (; i < end; i++) {
        int2 r0 = __ldcs(&g_edge[i]);
        int s0 = r0.x;
        float e0 = __int_as_float(r0.y);
        float lg0 = lrelu(g_als[s0 * 8 + head] + ald + e0 * we);
        float nm = fmaxf(m, lg0);
        float sc = __expf(m - nm);
        float p0 = __expf(lg0 - nm);
        psum = psum * sc + p0;
        acc = acc * sc + p0 * x[s0 * 4 + c];
        m = nm;
    }

    float inv = 1.0f / (psum + 1e-16f);
    float aggv = acc * inv;
    int base = l & ~3;
    float a0 = __shfl_sync(0xffffffffu, aggv, base);
    float a1 = __shfl_sync(0xffffffffu, aggv, base + 1);
    float a2 = __shfl_sync(0xffffffffu, aggv, base + 2);
    float a3 = __shfl_sync(0xffffffffu, aggv, base + 3);

    float o[8];
#pragma unroll
    for (int cc = 0; cc < 8; cc++) {
        int ch = l * 8 + cc;
        float v = fmaf(a0, W1[ch],
                  fmaf(a1, W1[256 + ch],
                  fmaf(a2, W1[512 + ch],
                  fmaf(a3, W1[768 + ch], bias[ch]))));
        o[cc] = fmaxf(v, 0.0f);
    }
    __stcs((float4*)(g_o + n * 256 + l * 8),     make_float4(o[0], o[1], o[2], o[3]));
    __stcs((float4*)(g_o + n * 256 + l * 8 + 4), make_float4(o[4], o[5], o[6], o[7]));
}

// ---------------- node attention logits for layers 2,3 (warp per node) --------
__global__ void k_nodeatt(const float* __restrict__ as_, const float* __restrict__ ad_,
                          const float* __restrict__ We, const float* __restrict__ ae) {
    if (blockIdx.x == gridDim.x - 1) {
        int t = threadIdx.x;
        int h = t >> 5, lane = t & 31;
        float v = We[t] * ae[t];
        for (int o = 16; o > 0; o >>= 1) v += __shfl_xor_sync(0xffffffffu, v, o);
        if (lane == 0) g_we[h] = v;
        return;
    }
    int warp = (blockIdx.x * blockDim.x + threadIdx.x) >> 5;
    if (warp >= NN) return;
    int n = warp;
    int l = threadIdx.x & 31;
    uint4 hv = *(const uint4*)(g_h2 + n * 128 + l * 4);
    float f[8];
    unp8(hv, f);
    const float* asp = as_ + l * 8;
    const float* adp = ad_ + l * 8;
    float s = 0.f, d = 0.f;
#pragma unroll
    for (int q = 0; q < 8; q++) {
        s = fmaf(f[q], asp[q], s);
        d = fmaf(f[q], adp[q], d);
    }
    s += __shfl_xor_sync(0xffffffffu, s, 1);
    s += __shfl_xor_sync(0xffffffffu, s, 2);
    d += __shfl_xor_sync(0xffffffffu, d, 1);
    d += __shfl_xor_sync(0xffffffffu, d, 2);
    if ((l & 3) == 0) {
        g_als[n * 8 + (l >> 2)] = s;
        g_ald[n * 8 + (l >> 2)] = d;
    }
}

// ---------------- TF32 tensor-core GEMM: g_h2 = fp16(g_o @ W) -----------------
__global__ void __launch_bounds__(256, 2) k_gemm_tf32(const float* __restrict__ W,
                                                      int M) {
    __shared__ float As[32][136];   // [k][row]
    __shared__ float Bs[32][136];   // [k][col]
    const float* A = g_o;

    int tid = threadIdx.x;
    int rowBase = blockIdx.y * 128;
    int colBase = blockIdx.x * 128;

    int wid = tid >> 5, lane = tid & 31;
    int wm = wid & 3, wn = wid >> 2;            // 4x2 warp grid
    int gid = lane >> 2, tg = lane & 3;

    int arow = tid >> 1, ak4 = (tid & 1) * 4;
    int bk = tid >> 3,  bn4 = (tid & 7) * 4;
    bool aval = (rowBase + arow) < M;
    const float* Aptr = A + (rowBase + arow) * 256 + ak4;
    const float* Wp   = W + bk * 256 + colBase + bn4;

    float acc[2][8][4];
#pragma unroll
    for (int i = 0; i < 2; i++)
#pragma unroll
        for (int j = 0; j < 8; j++)
#pragma unroll
            for (int q = 0; q < 4; q++) acc[i][j][q] = 0.0f;

    float4 ar[4], br[4];
#pragma unroll
    for (int u = 0; u < 4; u++) {
        ar[u] = aval ? *(const float4*)(Aptr + u * 8)
                     : make_float4(0.f, 0.f, 0.f, 0.f);
        br[u] = *(const float4*)(Wp + u * 32);
    }

#pragma unroll
    for (int it = 0; it < 8; it++) {
#pragma unroll
        for (int u = 0; u < 4; u++) {
            int kb = u * 8 + ak4;
            As[kb + 0][arow] = to_tf32(ar[u].x);
            As[kb + 1][arow] = to_tf32(ar[u].y);
            As[kb + 2][arow] = to_tf32(ar[u].z);
            As[kb + 3][arow] = to_tf32(ar[u].w);
            float4 bv = br[u];
            bv.x = to_tf32(bv.x); bv.y = to_tf32(bv.y);
            bv.z = to_tf32(bv.z); bv.w = to_tf32(bv.w);
            *(float4*)&Bs[bk][u * 32 + bn4] = bv;
        }
        __syncthreads();
        if (it < 7) {
            const float* Ap2 = Aptr + (it + 1) * 32;
            const float* Wp2 = Wp + (it + 1) * 32 * 256;
#pragma unroll
            for (int u = 0; u < 4; u++) {
                ar[u] = aval ? *(const float4*)(Ap2 + u * 8)
                             : make_float4(0.f, 0.f, 0.f, 0.f);
                br[u] = *(const float4*)(Wp2 + u * 32);
            }
        }
#pragma unroll
        for (int kt = 0; kt < 4; kt++) {
            int k0 = kt * 8 + tg;
            unsigned a[2][4];
#pragma unroll
            for (int i = 0; i < 2; i++) {
                int rb = wm * 32 + i * 16 + gid;
                a[i][0] = __float_as_uint(As[k0][rb]);
                a[i][1] = __float_as_uint(As[k0][rb + 8]);
                a[i][2] = __float_as_uint(As[k0 + 4][rb]);
                a[i][3] = __float_as_uint(As[k0 + 4][rb + 8]);
            }
            unsigned b[8][2];
#pragma unroll
            for (int j = 0; j < 8; j++) {
                int cb = wn * 64 + j * 8 + gid;
                b[j][0] = __float_as_uint(Bs[k0][cb]);
                b[j][1] = __float_as_uint(Bs[k0 + 4][cb]);
            }
#pragma unroll
            for (int i = 0; i < 2; i++)
#pragma unroll
                for (int j = 0; j < 8; j++) mma_tf32(acc[i][j], a[i], b[j]);
        }
        __syncthreads();
    }

#pragma unroll
    for (int i = 0; i < 2; i++) {
        int r0 = rowBase + wm * 32 + i * 16 + gid;
        int r1 = r0 + 8;
#pragma unroll
        for (int j = 0; j < 8; j++) {
            int col = colBase + wn * 64 + j * 8 + tg * 2;   // even
            if (r0 < M)
                g_h2[r0 * 128 + (col >> 1)] = __floats2half2_rn(acc[i][j][0], acc[i][j][1]);
            if (r1 < M)
                g_h2[r1 * 128 + (col >> 1)] = __floats2half2_rn(acc[i][j][2], acc[i][j][3]);
        }
    }
}

// ---------------- fused attention + aggregation (layers 2,3, self-loops) ------
// One warp per dst node, online softmax; fp16 h-gather (one uint4 per edge/lane).
// reset!=0 (layer 3): also re-zero g_cnt/g_easum/g_bflag for the next launch.
__global__ void __launch_bounds__(256) k_attn(const float* __restrict__ bias,
                                              float* __restrict__ outp, int reset) {
    int warp = (blockIdx.x * blockDim.x + threadIdx.x) >> 5;
    if (warp >= NN) return;
    int n = warp;
    int l = threadIdx.x & 31;
    int head = l >> 2;

    float we = g_we[head];
    float ald = g_ald[n * 8 + head];
    int start = g_rowptr[n], end = g_rowptr[n + 1];

    // self-loop init (fill_value='mean')
    float easum = g_easum[n];
    float le = easum / fmaxf((float)(end - start), 1.0f);
    float m = lrelu(g_als[n * 8 + head] + ald + le * we);
    float psum = 1.0f;
    float acc[8];
    {
        uint4 hv = *(const uint4*)(g_h2 + n * 128 + l * 4);
        unp8(hv, acc);
    }

    int i = start;
    for (; i + 2 <= end; i += 2) {
        int2 r0 = __ldcs(&g_edge[i]), r1 = __ldcs(&g_edge[i + 1]);
        int s0 = r0.x, s1 = r1.x;
        float e0 = __int_as_float(r0.y), e1 = __int_as_float(r1.y);
        float al0 = g_als[s0 * 8 + head], al1 = g_als[s1 * 8 + head];
        uint4 v0 = *(const uint4*)(g_h2 + s0 * 128 + l * 4);
        uint4 v1 = *(const uint4*)(g_h2 + s1 * 128 + l * 4);
        float f0[8], f1[8];
        unp8(v0, f0);
        unp8(v1, f1);
        float lg0 = lrelu(al0 + ald + e0 * we);
        float lg1 = lrelu(al1 + ald + e1 * we);
        float nm = fmaxf(m, fmaxf(lg0, lg1));
        float sc = __expf(m - nm);
        float p0 = __expf(lg0 - nm);
        float p1 = __expf(lg1 - nm);
        psum = psum * sc + p0 + p1;
#pragma unroll
        for (int q = 0; q < 8; q++)
            acc[q] = acc[q] * sc + p0 * f0[q] + p1 * f1[q];
        m = nm;
    }
    if (i < end) {
        int2 r0 = __ldcs(&g_edge[i]);
        int s0 = r0.x;
        float e0 = __int_as_float(r0.y);
        float lg0 = lrelu(g_als[s0 * 8 + head] + ald + e0 * we);
        uint4 v0 = *(const uint4*)(g_h2 + s0 * 128 + l * 4);
        float f0[8];
        unp8(v0, f0);
        float nm = fmaxf(m, lg0);
        float sc = __expf(m - nm);
        float p0 = __expf(lg0 - nm);
        psum = psum * sc + p0;
#pragma unroll
        for (int q = 0; q < 8; q++)
            acc[q] = acc[q] * sc + p0 * f0[q];
    }

    float inv = 1.0f / (psum + 1e-16f);
    const float* bp = bias + l * 8;
    float4 o0 = make_float4(fmaxf(acc[0] * inv + bp[0], 0.f),
                            fmaxf(acc[1] * inv + bp[1], 0.f),
                            fmaxf(acc[2] * inv + bp[2], 0.f),
                            fmaxf(acc[3] * inv + bp[3], 0.f));
    float4 o1 = make_float4(fmaxf(acc[4] * inv + bp[4], 0.f),
                            fmaxf(acc[5] * inv + bp[5], 0.f),
                            fmaxf(acc[6] * inv + bp[6], 0.f),
                            fmaxf(acc[7] * inv + bp[7], 0.f));
    __stcs((float4*)(outp + n * 256 + l * 8),     o0);
    __stcs((float4*)(outp + n * 256 + l * 8 + 4), o1);

    if (reset && l == 0) {              // leave globals clean for next launch
        g_cnt[n] = 0;
        g_easum[n] = 0.0f;
        if (n < 64) g_bflag[n] = 0;
    }
}

// ---------------- launch ------------------------------------------------------
extern "C" void kernel_launch(void* const* d_in, const int* in_sizes, int n_in,
                              void* d_out, int out_size) {
    const float* x   = (const float*)d_in[0];
    const int*   ei  = (const int*)d_in[1];
    const float* ea  = (const float*)d_in[2];
    const float* W1  = (const float*)d_in[3];
    const float* as1 = (const float*)d_in[4];
    const float* ad1 = (const float*)d_in[5];
    const float* We1 = (const float*)d_in[6];
    const float* ae1 = (const float*)d_in[7];
    const float* b1  = (const float*)d_in[8];
    const float* W2  = (const float*)d_in[9];
    const float* as2 = (const float*)d_in[10];
    const float* ad2 = (const float*)d_in[11];
    const float* We2 = (const float*)d_in[12];
    const float* ae2 = (const float*)d_in[13];
    const float* b2  = (const float*)d_in[14];
    const float* W3  = (const float*)d_in[15];
    const float* as3 = (const float*)d_in[16];
    const float* ad3 = (const float*)d_in[17];
    const float* We3 = (const float*)d_in[18];
    const float* ae3 = (const float*)d_in[19];
    const float* b3  = (const float*)d_in[20];
    float* out = (float*)d_out;

    const int nblkE   = (EE + 255) / 256;          // 3125
    const int scanBlk = (NN + 1023) / 1024;        // 49
    const int attnBlk = (NN * 32 + 255) / 256;     // 6250

    // 0: layer-1 node logits + g_we + histogram (counters zeroed by prev launch)
    k_front<<<NA1BLK + HISTBLK, 256>>>(x, W1, as1, ad1, We1, ae1, ei, ea);
    // 1: single-kernel prefix scan
    k_scan<<<scanBlk, 1024>>>();
    // 2: CSR scatter
    k_build<<<nblkE, 256>>>(ei, ea);
    // 3: layer-1 attention (profiled launch)
    k_attn1<<<attnBlk, 256>>>(x, W1, b1);

    dim3 gGemm(2, (NN + 127) / 128);
    float* g_o_ptr = nullptr;
    cudaGetSymbolAddress((void**)&g_o_ptr, g_o);

    // layer 2
    k_gemm_tf32<<<gGemm, 256>>>(W2, NN);
    k_nodeatt<<<attnBlk + 1, 256>>>(as2, ad2, We2, ae2);
    k_attn<<<attnBlk, 256>>>(b2, g_o_ptr, 0);

    // layer 3 -> d_out (+ reset counters for next launch)
    k_gemm_tf32<<<gGemm, 256>>>(W3, NN);
    k_nodeatt<<<attnBlk + 1, 256>>>(as3, ad3, We3, ae3);
    k_attn<<<attnBlk, 256>>>(b3, out, 1);
}

// round 7
// speedup vs baseline: 1.1211x; 1.0119x over previous
#include <cuda_runtime.h>
#include <cuda_fp16.h>
#include <math.h>

// Problem constants (fixed shapes per reference)
#define NN 50000
#define EE 800000
#define HH 8
#define HC 256
#define SLOPE 0.2f

// ---------------- static device scratch (no allocations allowed) --------------
__device__ __half2 g_h2[NN * HC / 2]; // projected features (fp16, 128 half2/row)
__device__ float g_o[NN * HC];        // layer output (input to next layer, fp32)
__device__ float g_als[NN * HH];      // per-node src attention logits
__device__ float g_ald[NN * HH];      // per-node dst attention logits
__device__ float g_we[HH];            // edge attention weight per head
__device__ int   g_rowptr[NN + 1];
__device__ int   g_cnt[NN];           // zeroed by previous launch's tail (or static init)
__device__ int   g_tmp[NN];           // build cursor (init'd by scan)
__device__ int2  g_edge[EE];          // CSR-ordered (src, edge_attr bits)
__device__ float g_easum[NN];         // sum of incoming edge attr per node
__device__ int   g_bsum[64];
__device__ int   g_bflag[64];         // scan lookback flags (reset by attn tail)
__device__ int   g_barrier;           // grid barrier for scanbuild (reset by attn tail)

// ---------------- helpers ------------------------------------------------------
__device__ __forceinline__ float to_tf32(float x) {
    unsigned r;
    asm("cvt.rn.tf32.f32 %0,%1;" : "=r"(r) : "f"(x));
    return __uint_as_float(r);
}
__device__ __forceinline__ void mma_tf32(float* c, const unsigned* a, const unsigned* b) {
    asm volatile(
        "mma.sync.aligned.m16n8k8.row.col.f32.tf32.tf32.f32 "
        "{%0,%1,%2,%3},{%4,%5,%6,%7},{%8,%9},{%0,%1,%2,%3};"
        : "+f"(c[0]), "+f"(c[1]), "+f"(c[2]), "+f"(c[3])
        : "r"(a[0]), "r"(a[1]), "r"(a[2]), "r"(a[3]), "r"(b[0]), "r"(b[1]));
}
__device__ __forceinline__ float lrelu(float v) {
    return (v > 0.0f) ? v : SLOPE * v;
}
// f32x2 packed math
__device__ __forceinline__ unsigned long long splat2(float x) {
    unsigned long long r;
    asm("mov.b64 %0,{%1,%1};" : "=l"(r) : "f"(x));
    return r;
}
__device__ __forceinline__ unsigned long long pack2(float x, float y) {
    unsigned long long r;
    asm("mov.b64 %0,{%1,%2};" : "=l"(r) : "f"(x), "f"(y));
    return r;
}
__device__ __forceinline__ unsigned long long fma2(unsigned long long a,
                                                   unsigned long long b,
                                                   unsigned long long c) {
    unsigned long long d;
    asm("fma.rn.f32x2 %0,%1,%2,%3;" : "=l"(d) : "l"(a), "l"(b), "l"(c));
    return d;
}
__device__ __forceinline__ float2 unpk(unsigned long long v) {
    float2 r;
    asm("mov.b64 {%0,%1},%2;" : "=f"(r.x), "=f"(r.y) : "l"(v));
    return r;
}

// ---------------- front kernel: layer-1 node logits + g_we + histogram --------
#define NA1BLK 1563
#define HISTBLK 3125
__global__ void __launch_bounds__(256) k_front(
    const float* __restrict__ x, const float* __restrict__ W1,
    const float* __restrict__ as_, const float* __restrict__ ad_,
    const float* __restrict__ We, const float* __restrict__ ae,
    const int* __restrict__ ei, const float* __restrict__ ea) {
    int b = blockIdx.x;
    int t = threadIdx.x;
    if (b >= NA1BLK) {
        int e = (b - NA1BLK) * 256 + t;
        if (e < EE) {
            int d = ei[EE + e];
            atomicAdd(&g_cnt[d], 1);
            atomicAdd(&g_easum[d], ea[e]);
        }
        return;
    }
    __shared__ float svs[4][8], svd[4][8];
    int h = t >> 5, lane = t & 31;
    {
        float asv = as_[t], adv = ad_[t];
#pragma unroll
        for (int k = 0; k < 4; k++) {
            float w = W1[k * 256 + t];
            float s = w * asv, d = w * adv;
            for (int o = 16; o > 0; o >>= 1) {
                s += __shfl_xor_sync(0xffffffffu, s, o);
                d += __shfl_xor_sync(0xffffffffu, d, o);
            }
            if (lane == 0) { svs[k][h] = s; svd[k][h] = d; }
        }
        if (b == 0) {
            float v = We[t] * ae[t];
            for (int o = 16; o > 0; o >>= 1) v += __shfl_xor_sync(0xffffffffu, v, o);
            if (lane == 0) g_we[h] = v;
        }
    }
    __syncthreads();
    int idx = b * 256 + t;
    if (idx >= NN * 8) return;
    int n = idx >> 3, hh = idx & 7;
    float x0 = x[n * 4], x1 = x[n * 4 + 1], x2 = x[n * 4 + 2], x3 = x[n * 4 + 3];
    g_als[idx] = x0 * svs[0][hh] + x1 * svs[1][hh] + x2 * svs[2][hh] + x3 * svs[3][hh];
    g_ald[idx] = x0 * svd[0][hh] + x1 * svd[1][hh] + x2 * svd[2][hh] + x3 * svd[3][hh];
}

// ---------------- fused scan + CSR build (grid barrier; 49 blocks resident) ----
__global__ void k_scanbuild(const int* __restrict__ ei, const float* __restrict__ ea) {
    __shared__ int s[1024];
    __shared__ int s_off;
    int bid = blockIdx.x, tid = threadIdx.x;
    int i = bid * 1024 + tid;
    int v = (i < NN) ? g_cnt[i] : 0;
    s[tid] = v;
    __syncthreads();
    for (int off = 1; off < 1024; off <<= 1) {
        int t = (tid >= off) ? s[tid - off] : 0;
        __syncthreads();
        s[tid] += t;
        __syncthreads();
    }
    if (tid == 1023) {                  // publish block aggregate
        g_bsum[bid] = s[1023];
        __threadfence();
        atomicExch(&g_bflag[bid], 1);
    }
    if (tid < 32) {                     // lookback: sum predecessor aggregates
        int sum = 0;
        for (int p = tid; p < bid; p += 32) {
            while (atomicAdd(&g_bflag[p], 0) == 0) {}
            sum += atomicAdd(&g_bsum[p], 0);
        }
        for (int o = 16; o > 0; o >>= 1) sum += __shfl_xor_sync(0xffffffffu, sum, o);
        if (tid == 0) s_off = sum;
    }
    if (bid == 0 && tid == 0) g_rowptr[NN] = EE;
    __syncthreads();
    if (i < NN) {
        int r = s[tid] - v + s_off;     // exclusive prefix
        g_rowptr[i] = r;
        g_tmp[i] = r;                   // running cursor for build phase
    }
    // ---- grid barrier (all 49 blocks co-resident in wave 1) ----
    __threadfence();
    __syncthreads();
    if (tid == 0) {
        atomicAdd(&g_barrier, 1);
        while (atomicAdd(&g_barrier, 0) < (int)gridDim.x) {}
    }
    __syncthreads();
    // ---- build phase: grid-stride scatter ----
    int nthr = gridDim.x * 1024;
    for (int e = bid * 1024 + tid; e < EE; e += nthr) {
        int d = ei[EE + e];
        int pos = atomicAdd(&g_tmp[d], 1);
        int2 rec;
        rec.x = ei[e];
        rec.y = __float_as_int(ea[e]);
        g_edge[pos] = rec;
    }
}

// ---------------- layer-1 fused attention (group-parallel, rank-4) ------------
// Lane l: group g=l>>3 (4 edge-parallel groups), head h=l&7.
// Each group runs an independent online softmax over its edge subset; exact
// merge at the end. Per 4 edges: 3 LDG warp-instructions (vs 12 before).
__global__ void __launch_bounds__(256) k_attn1(
    const float* __restrict__ x, const float* __restrict__ W1,
    const float* __restrict__ bias) {
    int warp = (blockIdx.x * blockDim.x + threadIdx.x) >> 5;
    if (warp >= NN) return;
    int n = warp;
    int l = threadIdx.x & 31;
    int g = l >> 3, h = l & 7;

    float we = g_we[h];
    float ald = g_ald[n * 8 + h];
    int start = g_rowptr[n], end = g_rowptr[n + 1];

    float m = -1e30f, psum = 0.0f;
    float4 acc = make_float4(0.f, 0.f, 0.f, 0.f);
    for (int i = start + g; i < end; i += 4) {
        int2 r = g_edge[i];
        int s = r.x;
        float ev = __int_as_float(r.y);
        float al = g_als[s * 8 + h];
        float4 xv = *(const float4*)(x + s * 4);
        float lg = lrelu(al + ald + ev * we);
        float nm = fmaxf(m, lg);
        float sc = __expf(m - nm);
        float p = __expf(lg - nm);
        psum = psum * sc + p;
        acc.x = acc.x * sc + p * xv.x;
        acc.y = acc.y * sc + p * xv.y;
        acc.z = acc.z * sc + p * xv.z;
        acc.w = acc.w * sc + p * xv.w;
        m = nm;
    }
    // exact merge across the 4 groups (xor 8, xor 16)
#pragma unroll
    for (int off = 8; off <= 16; off <<= 1) {
        float mo  = __shfl_xor_sync(0xffffffffu, m, off);
        float pso = __shfl_xor_sync(0xffffffffu, psum, off);
        float ax  = __shfl_xor_sync(0xffffffffu, acc.x, off);
        float ay  = __shfl_xor_sync(0xffffffffu, acc.y, off);
        float az  = __shfl_xor_sync(0xffffffffu, acc.z, off);
        float aw  = __shfl_xor_sync(0xffffffffu, acc.w, off);
        float M = fmaxf(m, mo);
        float e1 = __expf(m - M);
        float e2 = __expf(mo - M);
        psum = psum * e1 + pso * e2;
        acc.x = acc.x * e1 + ax * e2;
        acc.y = acc.y * e1 + ay * e2;
        acc.z = acc.z * e1 + az * e2;
        acc.w = acc.w * e1 + aw * e2;
        m = M;
    }

    float inv = 1.0f / (psum + 1e-16f);
    float4 aggv = make_float4(acc.x * inv, acc.y * inv, acc.z * inv, acc.w * inv);
    // lane l needs agg for head l>>2; source lane (l>>2) holds head (l>>2)
    int src = l >> 2;
    float a0 = __shfl_sync(0xffffffffu, aggv.x, src);
    float a1 = __shfl_sync(0xffffffffu, aggv.y, src);
    float a2 = __shfl_sync(0xffffffffu, aggv.z, src);
    float a3 = __shfl_sync(0xffffffffu, aggv.w, src);

    float o[8];
#pragma unroll
    for (int cc = 0; cc < 8; cc++) {
        int ch = l * 8 + cc;
        float v = fmaf(a0, W1[ch],
                  fmaf(a1, W1[256 + ch],
                  fmaf(a2, W1[512 + ch],
                  fmaf(a3, W1[768 + ch], bias[ch]))));
        o[cc] = fmaxf(v, 0.0f);
    }
    __stcs((float4*)(g_o + n * 256 + l * 8),     make_float4(o[0], o[1], o[2], o[3]));
    __stcs((float4*)(g_o + n * 256 + l * 8 + 4), make_float4(o[4], o[5], o[6], o[7]));
}

// ---------------- node attention logits for layers 2,3 (warp per node) --------
__global__ void k_nodeatt(const float* __restrict__ as_, const float* __restrict__ ad_,
                          const float* __restrict__ We, const float* __restrict__ ae) {
    if (blockIdx.x == gridDim.x - 1) {
        int t = threadIdx.x;
        int h = t >> 5, lane = t & 31;
        float v = We[t] * ae[t];
        for (int o = 16; o > 0; o >>= 1) v += __shfl_xor_sync(0xffffffffu, v, o);
        if (lane == 0) g_we[h] = v;
        return;
    }
    int warp = (blockIdx.x * blockDim.x + threadIdx.x) >> 5;
    if (warp >= NN) return;
    int n = warp;
    int l = threadIdx.x & 31;
    uint4 hv = *(const uint4*)(g_h2 + n * 128 + l * 4);
    float f[8];
    {
        float2 c0 = __half22float2(*(__half2*)&hv.x);
        float2 c1 = __half22float2(*(__half2*)&hv.y);
        float2 c2 = __half22float2(*(__half2*)&hv.z);
        float2 c3 = __half22float2(*(__half2*)&hv.w);
        f[0] = c0.x; f[1] = c0.y; f[2] = c1.x; f[3] = c1.y;
        f[4] = c2.x; f[5] = c2.y; f[6] = c3.x; f[7] = c3.y;
    }
    const float* asp = as_ + l * 8;
    const float* adp = ad_ + l * 8;
    float s = 0.f, d = 0.f;
#pragma unroll
    for (int q = 0; q < 8; q++) {
        s = fmaf(f[q], asp[q], s);
        d = fmaf(f[q], adp[q], d);
    }
    s += __shfl_xor_sync(0xffffffffu, s, 1);
    s += __shfl_xor_sync(0xffffffffu, s, 2);
    d += __shfl_xor_sync(0xffffffffu, d, 1);
    d += __shfl_xor_sync(0xffffffffu, d, 2);
    if ((l & 3) == 0) {
        g_als[n * 8 + (l >> 2)] = s;
        g_ald[n * 8 + (l >> 2)] = d;
    }
}

// ---------------- TF32 tensor-core GEMM: g_h2 = fp16(g_o @ W) -----------------
__global__ void __launch_bounds__(256, 2) k_gemm_tf32(const float* __restrict__ W,
                                                      int M) {
    __shared__ float As[32][136];   // [k][row]
    __shared__ float Bs[32][136];   // [k][col]
    const float* A = g_o;

    int tid = threadIdx.x;
    int rowBase = blockIdx.y * 128;
    int colBase = blockIdx.x * 128;

    int wid = tid >> 5, lane = tid & 31;
    int wm = wid & 3, wn = wid >> 2;            // 4x2 warp grid
    int gid = lane >> 2, tg = lane & 3;

    int arow = tid >> 1, ak4 = (tid & 1) * 4;
    int bk = tid >> 3,  bn4 = (tid & 7) * 4;
    bool aval = (rowBase + arow) < M;
    const float* Aptr = A + (rowBase + arow) * 256 + ak4;
    const float* Wp   = W + bk * 256 + colBase + bn4;

    float acc[2][8][4];
#pragma unroll
    for (int i = 0; i < 2; i++)
#pragma unroll
        for (int j = 0; j < 8; j++)
#pragma unroll
            for (int q = 0; q < 4; q++) acc[i][j][q] = 0.0f;

    float4 ar[4], br[4];
#pragma unroll
    for (int u = 0; u < 4; u++) {
        ar[u] = aval ? *(const float4*)(Aptr + u * 8)
                     : make_float4(0.f, 0.f, 0.f, 0.f);
        br[u] = *(const float4*)(Wp + u * 32);
    }

#pragma unroll
    for (int it = 0; it < 8; it++) {
#pragma unroll
        for (int u = 0; u < 4; u++) {
            int kb = u * 8 + ak4;
            As[kb + 0][arow] = to_tf32(ar[u].x);
            As[kb + 1][arow] = to_tf32(ar[u].y);
            As[kb + 2][arow] = to_tf32(ar[u].z);
            As[kb + 3][arow] = to_tf32(ar[u].w);
            float4 bv = br[u];
            bv.x = to_tf32(bv.x); bv.y = to_tf32(bv.y);
            bv.z = to_tf32(bv.z); bv.w = to_tf32(bv.w);
            *(float4*)&Bs[bk][u * 32 + bn4] = bv;
        }
        __syncthreads();
        if (it < 7) {
            const float* Ap2 = Aptr + (it + 1) * 32;
            const float* Wp2 = Wp + (it + 1) * 32 * 256;
#pragma unroll
            for (int u = 0; u < 4; u++) {
                ar[u] = aval ? *(const float4*)(Ap2 + u * 8)
                             : make_float4(0.f, 0.f, 0.f, 0.f);
                br[u] = *(const float4*)(Wp2 + u * 32);
            }
        }
#pragma unroll
        for (int kt = 0; kt < 4; kt++) {
            int k0 = kt * 8 + tg;
            unsigned a[2][4];
#pragma unroll
            for (int i = 0; i < 2; i++) {
                int rb = wm * 32 + i * 16 + gid;
                a[i][0] = __float_as_uint(As[k0][rb]);
                a[i][1] = __float_as_uint(As[k0][rb + 8]);
                a[i][2] = __float_as_uint(As[k0 + 4][rb]);
                a[i][3] = __float_as_uint(As[k0 + 4][rb + 8]);
            }
            unsigned b[8][2];
#pragma unroll
            for (int j = 0; j < 8; j++) {
                int cb = wn * 64 + j * 8 + gid;
                b[j][0] = __float_as_uint(Bs[k0][cb]);
                b[j][1] = __float_as_uint(Bs[k0 + 4][cb]);
            }
#pragma unroll
            for (int i = 0; i < 2; i++)
#pragma unroll
                for (int j = 0; j < 8; j++) mma_tf32(acc[i][j], a[i], b[j]);
        }
        __syncthreads();
    }

#pragma unroll
    for (int i = 0; i < 2; i++) {
        int r0 = rowBase + wm * 32 + i * 16 + gid;
        int r1 = r0 + 8;
#pragma unroll
        for (int j = 0; j < 8; j++) {
            int col = colBase + wn * 64 + j * 8 + tg * 2;   // even
            if (r0 < M)
                g_h2[r0 * 128 + (col >> 1)] = __floats2half2_rn(acc[i][j][0], acc[i][j][1]);
            if (r1 < M)
                g_h2[r1 * 128 + (col >> 1)] = __floats2half2_rn(acc[i][j][2], acc[i][j][3]);
        }
    }
}

// ---------------- fused attention + aggregation (layers 2,3, self-loops) ------
// One warp per dst node, online softmax; fp16 gathers, f32x2 packed accumulate.
__global__ void __launch_bounds__(256) k_attn(const float* __restrict__ bias,
                                              float* __restrict__ outp, int reset) {
    int warp = (blockIdx.x * blockDim.x + threadIdx.x) >> 5;
    if (warp >= NN) return;
    int n = warp;
    int l = threadIdx.x & 31;
    int head = l >> 2;

    float we = g_we[head];
    float ald = g_ald[n * 8 + head];
    int start = g_rowptr[n], end = g_rowptr[n + 1];

    // self-loop init (fill_value='mean')
    float le = g_easum[n] / fmaxf((float)(end - start), 1.0f);
    float m = lrelu(g_als[n * 8 + head] + ald + le * we);
    float psum = 1.0f;
    unsigned long long acc2[4];
    {
        uint4 hv = *(const uint4*)(g_h2 + n * 128 + l * 4);
        const __half2* hp = (const __half2*)&hv;
#pragma unroll
        for (int j = 0; j < 4; j++) {
            float2 c = __half22float2(hp[j]);
            acc2[j] = pack2(c.x, c.y);
        }
    }

    int i = start;
    for (; i + 2 <= end; i += 2) {
        int2 r0 = __ldcs(&g_edge[i]), r1 = __ldcs(&g_edge[i + 1]);
        int s0 = r0.x, s1 = r1.x;
        float e0 = __int_as_float(r0.y), e1 = __int_as_float(r1.y);
        float al0 = g_als[s0 * 8 + head], al1 = g_als[s1 * 8 + head];
        uint4 v0 = *(const uint4*)(g_h2 + s0 * 128 + l * 4);
        uint4 v1 = *(const uint4*)(g_h2 + s1 * 128 + l * 4);
        float lg0 = lrelu(al0 + ald + e0 * we);
        float lg1 = lrelu(al1 + ald + e1 * we);
        float nm = fmaxf(m, fmaxf(lg0, lg1));
        float sc = __expf(m - nm);
        float p0 = __expf(lg0 - nm);
        float p1 = __expf(lg1 - nm);
        psum = psum * sc + p0 + p1;
        unsigned long long sc2 = splat2(sc), p02 = splat2(p0), p12 = splat2(p1);
        const __half2* h0 = (const __half2*)&v0;
        const __half2* h1 = (const __half2*)&v1;
#pragma unroll
        for (int j = 0; j < 4; j++) {
            float2 c0 = __half22float2(h0[j]);
            float2 c1 = __half22float2(h1[j]);
            unsigned long long w = fma2(pack2(c1.x, c1.y), p12, 0ull);
            w = fma2(pack2(c0.x, c0.y), p02, w);
            acc2[j] = fma2(acc2[j], sc2, w);
        }
        m = nm;
    }
    if (i < end) {
        int2 r0 = __ldcs(&g_edge[i]);
        int s0 = r0.x;
        float e0 = __int_as_float(r0.y);
        float lg0 = lrelu(g_als[s0 * 8 + head] + ald + e0 * we);
        uint4 v0 = *(const uint4*)(g_h2 + s0 * 128 + l * 4);
        float nm = fmaxf(m, lg0);
        float sc = __expf(m - nm);
        float p0 = __expf(lg0 - nm);
        psum = psum * sc + p0;
        unsigned long long sc2 = splat2(sc), p02 = splat2(p0);
        const __half2* h0 = (const __half2*)&v0;
#pragma unroll
        for (int j = 0; j < 4; j++) {
            float2 c0 = __half22float2(h0[j]);
            unsigned long long w = fma2(pack2(c0.x, c0.y), p02, 0ull);
            acc2[j] = fma2(acc2[j], sc2, w);
        }
    }

    float inv = 1.0f / (psum + 1e-16f);
    float2 q0 = unpk(acc2[0]), q1 = unpk(acc2[1]);
    float2 q2 = unpk(acc2[2]), q3 = unpk(acc2[3]);
    const float* bp = bias + l * 8;
    float4 o0 = make_float4(fmaxf(q0.x * inv + bp[0], 0.f),
                            fmaxf(q0.y * inv + bp[1], 0.f),
                            fmaxf(q1.x * inv + bp[2], 0.f),
                            fmaxf(q1.y * inv + bp[3], 0.f));
    float4 o1 = make_float4(fmaxf(q2.x * inv + bp[4], 0.f),
                            fmaxf(q2.y * inv + bp[5], 0.f),
                            fmaxf(q3.x * inv + bp[6], 0.f),
                            fmaxf(q3.y * inv + bp[7], 0.f));
    __stcs((float4*)(outp + n * 256 + l * 8),     o0);
    __stcs((float4*)(outp + n * 256 + l * 8 + 4), o1);

    if (reset && l == 0) {              // leave globals clean for next launch
        g_cnt[n] = 0;
        g_easum[n] = 0.0f;
        if (n < 64) g_bflag[n] = 0;
        if (n == 0) g_barrier = 0;
    }
}

// ---------------- launch ------------------------------------------------------
extern "C" void kernel_launch(void* const* d_in, const int* in_sizes, int n_in,
                              void* d_out, int out_size) {
    const float* x   = (const float*)d_in[0];
    const int*   ei  = (const int*)d_in[1];
    const float* ea  = (const float*)d_in[2];
    const float* W1  = (const float*)d_in[3];
    const float* as1 = (const float*)d_in[4];
    const float* ad1 = (const float*)d_in[5];
    const float* We1 = (const float*)d_in[6];
    const float* ae1 = (const float*)d_in[7];
    const float* b1  = (const float*)d_in[8];
    const float* W2  = (const float*)d_in[9];
    const float* as2 = (const float*)d_in[10];
    const float* ad2 = (const float*)d_in[11];
    const float* We2 = (const float*)d_in[12];
    const float* ae2 = (const float*)d_in[13];
    const float* b2  = (const float*)d_in[14];
    const float* W3  = (const float*)d_in[15];
    const float* as3 = (const float*)d_in[16];
    const float* ad3 = (const float*)d_in[17];
    const float* We3 = (const float*)d_in[18];
    const float* ae3 = (const float*)d_in[19];
    const float* b3  = (const float*)d_in[20];
    float* out = (float*)d_out;

    const int scanBlk = (NN + 1023) / 1024;        // 49
    const int attnBlk = (NN * 32 + 255) / 256;     // 6250

    // 0: layer-1 node logits + g_we + histogram
    k_front<<<NA1BLK + HISTBLK, 256>>>(x, W1, as1, ad1, We1, ae1, ei, ea);
    // 1: fused prefix scan + CSR scatter
    k_scanbuild<<<scanBlk, 1024>>>(ei, ea);
    // 2: layer-1 attention
    k_attn1<<<attnBlk, 256>>>(x, W1, b1);

    dim3 gGemm(2, (NN + 127) / 128);
    float* g_o_ptr = nullptr;
    cudaGetSymbolAddress((void**)&g_o_ptr, g_o);

    // layer 2  (3: gemm is the profiled launch)
    k_gemm_tf32<<<gGemm, 256>>>(W2, NN);
    k_nodeatt<<<attnBlk + 1, 256>>>(as2, ad2, We2, ae2);
    k_attn<<<attnBlk, 256>>>(b2, g_o_ptr, 0);

    // layer 3 -> d_out (+ reset counters for next launch)
    k_gemm_tf32<<<gGemm, 256>>>(W3, NN);
    k_nodeatt<<<attnBlk + 1, 256>>>(as3, ad3, We3, ae3);
    k_attn<<<attnBlk, 256>>>(b3, out, 1);
}

// round 9
// speedup vs baseline: 1.4202x; 1.2668x over previous
#include <cuda_runtime.h>
#include <cuda_fp16.h>
#include <math.h>

// Problem constants (fixed shapes per reference)
#define NN 50000
#define EE 800000
#define HH 8
#define HC 256
#define SLOPE 0.2f

// ---------------- static device scratch (no allocations allowed) --------------
__device__ __half2 g_h2[NN * HC / 2]; // projected features (fp16, 128 half2/row)
__device__ __half2 g_o2[NN * HC / 2]; // layer output (fp16, input to next GEMM)
__device__ float g_als[NN * HH];      // per-node src attention logits
__device__ float g_ald[NN * HH];      // per-node dst attention logits
__device__ float g_we[HH];            // edge attention weight per head
__device__ int   g_rowptr[NN + 1];
__device__ int   g_cnt[NN];           // zeroed by previous launch's tail (or static init)
__device__ int   g_tmp[NN];           // build cursor (init'd by scan)
__device__ int2  g_edge[EE];          // CSR-ordered (src, edge_attr bits)
__device__ float g_easum[NN];         // sum of incoming edge attr per node
__device__ int   g_bsum[64];
__device__ int   g_bflag[64];         // scan lookback flags (reset by attn tail)
__device__ int   g_barrier;           // grid barrier for scanbuild (reset by attn tail)

// ---------------- helpers ------------------------------------------------------
__device__ __forceinline__ float lrelu(float v) {
    return (v > 0.0f) ? v : SLOPE * v;
}
__device__ __forceinline__ void mma_f16(float* c, const unsigned* a, const unsigned* b) {
    asm volatile(
        "mma.sync.aligned.m16n8k16.row.col.f32.f16.f16.f32 "
        "{%0,%1,%2,%3},{%4,%5,%6,%7},{%8,%9},{%0,%1,%2,%3};"
        : "+f"(c[0]), "+f"(c[1]), "+f"(c[2]), "+f"(c[3])
        : "r"(a[0]), "r"(a[1]), "r"(a[2]), "r"(a[3]), "r"(b[0]), "r"(b[1]));
}
__device__ __forceinline__ void ldsm4(unsigned& r0, unsigned& r1, unsigned& r2,
                                      unsigned& r3, unsigned addr) {
    asm volatile("ldmatrix.sync.aligned.m8n8.x4.shared.b16 {%0,%1,%2,%3},[%4];"
                 : "=r"(r0), "=r"(r1), "=r"(r2), "=r"(r3) : "r"(addr));
}
__device__ __forceinline__ void ldsm4t(unsigned& r0, unsigned& r1, unsigned& r2,
                                       unsigned& r3, unsigned addr) {
    asm volatile("ldmatrix.sync.aligned.m8n8.x4.trans.shared.b16 {%0,%1,%2,%3},[%4];"
                 : "=r"(r0), "=r"(r1), "=r"(r2), "=r"(r3) : "r"(addr));
}
// f32x2 packed math
__device__ __forceinline__ unsigned long long splat2(float x) {
    unsigned long long r;
    asm("mov.b64 %0,{%1,%1};" : "=l"(r) : "f"(x));
    return r;
}
__device__ __forceinline__ unsigned long long pack2(float x, float y) {
    unsigned long long r;
    asm("mov.b64 %0,{%1,%2};" : "=l"(r) : "f"(x), "f"(y));
    return r;
}
__device__ __forceinline__ unsigned long long fma2(unsigned long long a,
                                                   unsigned long long b,
                                                   unsigned long long c) {
    unsigned long long d;
    asm("fma.rn.f32x2 %0,%1,%2,%3;" : "=l"(d) : "l"(a), "l"(b), "l"(c));
    return d;
}
__device__ __forceinline__ float2 unpk(unsigned long long v) {
    float2 r;
    asm("mov.b64 {%0,%1},%2;" : "=f"(r.x), "=f"(r.y) : "l"(v));
    return r;
}

// ---------------- front kernel: layer-1 node logits + g_we + histogram --------
#define NA1BLK 1563
#define HISTBLK 3125
__global__ void __launch_bounds__(256) k_front(
    const float* __restrict__ x, const float* __restrict__ W1,
    const float* __restrict__ as_, const float* __restrict__ ad_,
    const float* __restrict__ We, const float* __restrict__ ae,
    const int* __restrict__ ei, const float* __restrict__ ea) {
    int b = blockIdx.x;
    int t = threadIdx.x;
    if (b >= NA1BLK) {
        int e = (b - NA1BLK) * 256 + t;
        if (e < EE) {
            int d = ei[EE + e];
            atomicAdd(&g_cnt[d], 1);
            atomicAdd(&g_easum[d], ea[e]);
        }
        return;
    }
    __shared__ float svs[4][8], svd[4][8];
    int h = t >> 5, lane = t & 31;
    {
        float asv = as_[t], adv = ad_[t];
#pragma unroll
        for (int k = 0; k < 4; k++) {
            float w = W1[k * 256 + t];
            float s = w * asv, d = w * adv;
            for (int o = 16; o > 0; o >>= 1) {
                s += __shfl_xor_sync(0xffffffffu, s, o);
                d += __shfl_xor_sync(0xffffffffu, d, o);
            }
            if (lane == 0) { svs[k][h] = s; svd[k][h] = d; }
        }
        if (b == 0) {
            float v = We[t] * ae[t];
            for (int o = 16; o > 0; o >>= 1) v += __shfl_xor_sync(0xffffffffu, v, o);
            if (lane == 0) g_we[h] = v;
        }
    }
    __syncthreads();
    int idx = b * 256 + t;
    if (idx >= NN * 8) return;
    int n = idx >> 3, hh = idx & 7;
    float x0 = x[n * 4], x1 = x[n * 4 + 1], x2 = x[n * 4 + 2], x3 = x[n * 4 + 3];
    g_als[idx] = x0 * svs[0][hh] + x1 * svs[1][hh] + x2 * svs[2][hh] + x3 * svs[3][hh];
    g_ald[idx] = x0 * svd[0][hh] + x1 * svd[1][hh] + x2 * svd[2][hh] + x3 * svd[3][hh];
}

// ---------------- fused scan + CSR build (grid barrier; 49 blocks resident) ----
__global__ void k_scanbuild(const int* __restrict__ ei, const float* __restrict__ ea) {
    __shared__ int s[1024];
    __shared__ int s_off;
    int bid = blockIdx.x, tid = threadIdx.x;
    int i = bid * 1024 + tid;
    int v = (i < NN) ? g_cnt[i] : 0;
    s[tid] = v;
    __syncthreads();
    for (int off = 1; off < 1024; off <<= 1) {
        int t = (tid >= off) ? s[tid - off] : 0;
        __syncthreads();
        s[tid] += t;
        __syncthreads();
    }
    if (tid == 1023) {
        g_bsum[bid] = s[1023];
        __threadfence();
        atomicExch(&g_bflag[bid], 1);
    }
    if (tid < 32) {
        int sum = 0;
        for (int p = tid; p < bid; p += 32) {
            while (atomicAdd(&g_bflag[p], 0) == 0) {}
            sum += atomicAdd(&g_bsum[p], 0);
        }
        for (int o = 16; o > 0; o >>= 1) sum += __shfl_xor_sync(0xffffffffu, sum, o);
        if (tid == 0) s_off = sum;
    }
    if (bid == 0 && tid == 0) g_rowptr[NN] = EE;
    __syncthreads();
    if (i < NN) {
        int r = s[tid] - v + s_off;
        g_rowptr[i] = r;
        g_tmp[i] = r;
    }
    __threadfence();
    __syncthreads();
    if (tid == 0) {
        atomicAdd(&g_barrier, 1);
        while (atomicAdd(&g_barrier, 0) < (int)gridDim.x) {}
    }
    __syncthreads();
    int nthr = gridDim.x * 1024;
    for (int e = bid * 1024 + tid; e < EE; e += nthr) {
        int d = ei[EE + e];
        int pos = atomicAdd(&g_tmp[d], 1);
        int2 rec;
        rec.x = ei[e];
        rec.y = __float_as_int(ea[e]);
        g_edge[pos] = rec;
    }
}

// ---------------- layer-1 fused attention (group-parallel, rank-4) ------------
__global__ void __launch_bounds__(256) k_attn1(
    const float* __restrict__ x, const float* __restrict__ W1,
    const float* __restrict__ bias) {
    int warp = (blockIdx.x * blockDim.x + threadIdx.x) >> 5;
    if (warp >= NN) return;
    int n = warp;
    int l = threadIdx.x & 31;
    int g = l >> 3, h = l & 7;

    float we = g_we[h];
    float ald = g_ald[n * 8 + h];
    int start = g_rowptr[n], end = g_rowptr[n + 1];

    float m = -1e30f, psum = 0.0f;
    float4 acc = make_float4(0.f, 0.f, 0.f, 0.f);
    for (int i = start + g; i < end; i += 4) {
        int2 r = g_edge[i];
        int s = r.x;
        float ev = __int_as_float(r.y);
        float al = g_als[s * 8 + h];
        float4 xv = *(const float4*)(x + s * 4);
        float lg = lrelu(al + ald + ev * we);
        float nm = fmaxf(m, lg);
        float sc = __expf(m - nm);
        float p = __expf(lg - nm);
        psum = psum * sc + p;
        acc.x = acc.x * sc + p * xv.x;
        acc.y = acc.y * sc + p * xv.y;
        acc.z = acc.z * sc + p * xv.z;
        acc.w = acc.w * sc + p * xv.w;
        m = nm;
    }
#pragma unroll
    for (int off = 8; off <= 16; off <<= 1) {
        float mo  = __shfl_xor_sync(0xffffffffu, m, off);
        float pso = __shfl_xor_sync(0xffffffffu, psum, off);
        float ax  = __shfl_xor_sync(0xffffffffu, acc.x, off);
        float ay  = __shfl_xor_sync(0xffffffffu, acc.y, off);
        float az  = __shfl_xor_sync(0xffffffffu, acc.z, off);
        float aw  = __shfl_xor_sync(0xffffffffu, acc.w, off);
        float M = fmaxf(m, mo);
        float e1 = __expf(m - M);
        float e2 = __expf(mo - M);
        psum = psum * e1 + pso * e2;
        acc.x = acc.x * e1 + ax * e2;
        acc.y = acc.y * e1 + ay * e2;
        acc.z = acc.z * e1 + az * e2;
        acc.w = acc.w * e1 + aw * e2;
        m = M;
    }

    float inv = 1.0f / (psum + 1e-16f);
    float4 aggv = make_float4(acc.x * inv, acc.y * inv, acc.z * inv, acc.w * inv);
    int src = l >> 2;
    float a0 = __shfl_sync(0xffffffffu, aggv.x, src);
    float a1 = __shfl_sync(0xffffffffu, aggv.y, src);
    float a2 = __shfl_sync(0xffffffffu, aggv.z, src);
    float a3 = __shfl_sync(0xffffffffu, aggv.w, src);

    float o[8];
#pragma unroll
    for (int cc = 0; cc < 8; cc++) {
        int ch = l * 8 + cc;
        float v = fmaf(a0, W1[ch],
                  fmaf(a1, W1[256 + ch],
                  fmaf(a2, W1[512 + ch],
                  fmaf(a3, W1[768 + ch], bias[ch]))));
        o[cc] = fmaxf(v, 0.0f);
    }
    // pack to fp16 and store 16B
    __half2 p0 = __floats2half2_rn(o[0], o[1]);
    __half2 p1 = __floats2half2_rn(o[2], o[3]);
    __half2 p2 = __floats2half2_rn(o[4], o[5]);
    __half2 p3 = __floats2half2_rn(o[6], o[7]);
    uint4 pk;
    pk.x = *(unsigned*)&p0; pk.y = *(unsigned*)&p1;
    pk.z = *(unsigned*)&p2; pk.w = *(unsigned*)&p3;
    __stcs((uint4*)(g_o2 + n * 128 + l * 4), pk);
}

// ---------------- node attention logits for layers 2,3 (warp per node) --------
__global__ void k_nodeatt(const float* __restrict__ as_, const float* __restrict__ ad_,
                          const float* __restrict__ We, const float* __restrict__ ae) {
    if (blockIdx.x == gridDim.x - 1) {
        int t = threadIdx.x;
        int h = t >> 5, lane = t & 31;
        float v = We[t] * ae[t];
        for (int o = 16; o > 0; o >>= 1) v += __shfl_xor_sync(0xffffffffu, v, o);
        if (lane == 0) g_we[h] = v;
        return;
    }
    int warp = (blockIdx.x * blockDim.x + threadIdx.x) >> 5;
    if (warp >= NN) return;
    int n = warp;
    int l = threadIdx.x & 31;
    uint4 hv = *(const uint4*)(g_h2 + n * 128 + l * 4);
    float f[8];
    {
        float2 c0 = __half22float2(*(__half2*)&hv.x);
        float2 c1 = __half22float2(*(__half2*)&hv.y);
        float2 c2 = __half22float2(*(__half2*)&hv.z);
        float2 c3 = __half22float2(*(__half2*)&hv.w);
        f[0] = c0.x; f[1] = c0.y; f[2] = c1.x; f[3] = c1.y;
        f[4] = c2.x; f[5] = c2.y; f[6] = c3.x; f[7] = c3.y;
    }
    const float* asp = as_ + l * 8;
    const float* adp = ad_ + l * 8;
    float s = 0.f, d = 0.f;
#pragma unroll
    for (int q = 0; q < 8; q++) {
        s = fmaf(f[q], asp[q], s);
        d = fmaf(f[q], adp[q], d);
    }
    s += __shfl_xor_sync(0xffffffffu, s, 1);
    s += __shfl_xor_sync(0xffffffffu, s, 2);
    d += __shfl_xor_sync(0xffffffffu, d, 1);
    d += __shfl_xor_sync(0xffffffffu, d, 2);
    if ((l & 3) == 0) {
        g_als[n * 8 + (l >> 2)] = s;
        g_ald[n * 8 + (l >> 2)] = d;
    }
}

// ---------------- FP16 tensor-core GEMM: g_h2 = fp16(g_o2 @ W) -----------------
// Block 128x128, k-chunk 32. 8 warps 4x2 (warp tile 32x64). mma.m16n8k16.f16,
// fragments via ldmatrix (A normal from [m][k], B trans from [k][n]).
__global__ void __launch_bounds__(256, 2) k_gemm_f16(const float* __restrict__ W,
                                                     int M) {
    __shared__ __half As[128][40];    // [m][k], 80B rows -> LDSM conflict-free
    __shared__ __half Bs[32][136];    // [k][n], 272B rows -> LDSM conflict-free
    const __half* A = (const __half*)g_o2;

    int tid = threadIdx.x;
    int rowBase = blockIdx.y * 128;
    int colBase = blockIdx.x * 128;
    int wid = tid >> 5, lane = tid & 31;
    int wm = wid & 3, wn = wid >> 2;            // 4x2 warp grid
    int gid = lane >> 2, tg = lane & 3;

    // staging mappings (A: 128 rows x 32 k = 4096 halves; 16 halves/thread)
    int arow = tid >> 1, ak = (tid & 1) * 16;   // A: 2x uint4 (16 halves) per thread
    int bn0 = (tid & 31) * 4, bk = tid >> 5;    // B: float4 per thread, 4 k-passes
    bool aval = (rowBase + arow) < M;
    const __half* Ap = A + (rowBase + arow) * 256 + ak;
    const float*  Wp = W + bk * 256 + colBase + bn0;

    float acc[2][8][4];
#pragma unroll
    for (int i = 0; i < 2; i++)
#pragma unroll
        for (int j = 0; j < 8; j++)
#pragma unroll
            for (int q = 0; q < 4; q++) acc[i][j][q] = 0.0f;

    uint4 an0, an1;
    float4 bn[4];
    an0 = aval ? *(const uint4*)Ap       : make_uint4(0u, 0u, 0u, 0u);
    an1 = aval ? *(const uint4*)(Ap + 8) : make_uint4(0u, 0u, 0u, 0u);
#pragma unroll
    for (int p = 0; p < 4; p++) bn[p] = *(const float4*)(Wp + p * 8 * 256);

#pragma unroll
    for (int it = 0; it < 8; it++) {
        // stage
        *(uint4*)&As[arow][ak]     = an0;
        *(uint4*)&As[arow][ak + 8] = an1;
#pragma unroll
        for (int p = 0; p < 4; p++) {
            __half2 h0 = __floats2half2_rn(bn[p].x, bn[p].y);
            __half2 h1 = __floats2half2_rn(bn[p].z, bn[p].w);
            uint2 u;
            u.x = *(unsigned*)&h0;
            u.y = *(unsigned*)&h1;
            *(uint2*)&Bs[bk + p * 8][bn0] = u;
        }
        __syncthreads();
        // prefetch next chunk
        if (it < 7) {
            const __half* Ap2 = Ap + (it + 1) * 32;
            const float*  Wp2 = Wp + (it + 1) * 32 * 256;
            an0 = aval ? *(const uint4*)Ap2       : make_uint4(0u, 0u, 0u, 0u);
            an1 = aval ? *(const uint4*)(Ap2 + 8) : make_uint4(0u, 0u, 0u, 0u);
#pragma unroll
            for (int p = 0; p < 4; p++) bn[p] = *(const float4*)(Wp2 + p * 8 * 256);
        }
        // compute: 2 k-steps of 16
#pragma unroll
        for (int ks = 0; ks < 2; ks++) {
            int k0 = ks * 16;
            unsigned a[2][4];
#pragma unroll
            for (int i = 0; i < 2; i++) {
                int row = wm * 32 + i * 16 + (lane & 15);
                int ko = k0 + ((lane >> 4) << 3);
                unsigned ad = (unsigned)__cvta_generic_to_shared(&As[row][ko]);
                ldsm4(a[i][0], a[i][1], a[i][2], a[i][3], ad);
            }
            unsigned b[8][2];
            {
                int kr = k0 + (lane & 7);
                int nb = ((lane >> 3) << 3);
                unsigned ad0 = (unsigned)__cvta_generic_to_shared(&Bs[kr][wn * 64 + nb]);
                unsigned ad1 = (unsigned)__cvta_generic_to_shared(&Bs[kr][wn * 64 + 32 + nb]);
                int kr2 = kr + 8;
                unsigned ad2 = (unsigned)__cvta_generic_to_shared(&Bs[kr2][wn * 64 + nb]);
                unsigned ad3 = (unsigned)__cvta_generic_to_shared(&Bs[kr2][wn * 64 + 32 + nb]);
                ldsm4t(b[0][0], b[1][0], b[2][0], b[3][0], ad0);
                ldsm4t(b[4][0], b[5][0], b[6][0], b[7][0], ad1);
                ldsm4t(b[0][1], b[1][1], b[2][1], b[3][1], ad2);
                ldsm4t(b[4][1], b[5][1], b[6][1], b[7][1], ad3);
            }
#pragma unroll
            for (int i = 0; i < 2; i++)
#pragma unroll
                for (int j = 0; j < 8; j++) mma_f16(acc[i][j], a[i], b[j]);
        }
        __syncthreads();
    }

    // epilogue -> fp16 g_h2
#pragma unroll
    for (int i = 0; i < 2; i++) {
        int r0 = rowBase + wm * 32 + i * 16 + gid;
        int r1 = r0 + 8;
#pragma unroll
        for (int j = 0; j < 8; j++) {
            int col = colBase + wn * 64 + j * 8 + tg * 2;   // even
            if (r0 < M)
                g_h2[r0 * 128 + (col >> 1)] = __floats2half2_rn(acc[i][j][0], acc[i][j][1]);
            if (r1 < M)
                g_h2[r1 * 128 + (col >> 1)] = __floats2half2_rn(acc[i][j][2], acc[i][j][3]);
        }
    }
}

// ---------------- fused attention + aggregation (layers 2,3, self-loops) ------
// One warp per dst node, online softmax; fp16 gathers, f32x2 packed accumulate.
// outp == nullptr -> write fp16 to g_o2 (layer 2); else fp32 to outp (layer 3).
__global__ void __launch_bounds__(256) k_attn(const float* __restrict__ bias,
                                              float* __restrict__ outp, int reset) {
    int warp = (blockIdx.x * blockDim.x + threadIdx.x) >> 5;
    if (warp >= NN) return;
    int n = warp;
    int l = threadIdx.x & 31;
    int head = l >> 2;

    float we = g_we[head];
    float ald = g_ald[n * 8 + head];
    int start = g_rowptr[n], end = g_rowptr[n + 1];

    float le = g_easum[n] / fmaxf((float)(end - start), 1.0f);
    float m = lrelu(g_als[n * 8 + head] + ald + le * we);
    float psum = 1.0f;
    unsigned long long acc2[4];
    {
        uint4 hv = *(const uint4*)(g_h2 + n * 128 + l * 4);
        const __half2* hp = (const __half2*)&hv;
#pragma unroll
        for (int j = 0; j < 4; j++) {
            float2 c = __half22float2(hp[j]);
            acc2[j] = pack2(c.x, c.y);
        }
    }

    int i = start;
    for (; i + 2 <= end; i += 2) {
        int2 r0 = __ldcs(&g_edge[i]), r1 = __ldcs(&g_edge[i + 1]);
        int s0 = r0.x, s1 = r1.x;
        float e0 = __int_as_float(r0.y), e1 = __int_as_float(r1.y);
        float al0 = g_als[s0 * 8 + head], al1 = g_als[s1 * 8 + head];
        uint4 v0 = *(const uint4*)(g_h2 + s0 * 128 + l * 4);
        uint4 v1 = *(const uint4*)(g_h2 + s1 * 128 + l * 4);
        float lg0 = lrelu(al0 + ald + e0 * we);
        float lg1 = lrelu(al1 + ald + e1 * we);
        float nm = fmaxf(m, fmaxf(lg0, lg1));
        float sc = __expf(m - nm);
        float p0 = __expf(lg0 - nm);
        float p1 = __expf(lg1 - nm);
        psum = psum * sc + p0 + p1;
        unsigned long long sc2 = splat2(sc), p02 = splat2(p0), p12 = splat2(p1);
        const __half2* h0 = (const __half2*)&v0;
        const __half2* h1 = (const __half2*)&v1;
#pragma unroll
        for (int j = 0; j < 4; j++) {
            float2 c0 = __half22float2(h0[j]);
            float2 c1 = __half22float2(h1[j]);
            unsigned long long w = fma2(pack2(c1.x, c1.y), p12, 0ull);
            w = fma2(pack2(c0.x, c0.y), p02, w);
            acc2[j] = fma2(acc2[j], sc2, w);
        }
        m = nm;
    }
    if (i < end) {
        int2 r0 = __ldcs(&g_edge[i]);
        int s0 = r0.x;
        float e0 = __int_as_float(r0.y);
        float lg0 = lrelu(g_als[s0 * 8 + head] + ald + e0 * we);
        uint4 v0 = *(const uint4*)(g_h2 + s0 * 128 + l * 4);
        float nm = fmaxf(m, lg0);
        float sc = __expf(m - nm);
        float p0 = __expf(lg0 - nm);
        psum = psum * sc + p0;
        unsigned long long sc2 = splat2(sc), p02 = splat2(p0);
        const __half2* h0 = (const __half2*)&v0;
#pragma unroll
        for (int j = 0; j < 4; j++) {
            float2 c0 = __half22float2(h0[j]);
            unsigned long long w = fma2(pack2(c0.x, c0.y), p02, 0ull);
            acc2[j] = fma2(acc2[j], sc2, w);
        }
    }

    float inv = 1.0f / (psum + 1e-16f);
    float2 q0 = unpk(acc2[0]), q1 = unpk(acc2[1]);
    float2 q2 = unpk(acc2[2]), q3 = unpk(acc2[3]);
    const float* bp = bias + l * 8;
    float o0 = fmaxf(q0.x * inv + bp[0], 0.f);
    float o1 = fmaxf(q0.y * inv + bp[1], 0.f);
    float o2 = fmaxf(q1.x * inv + bp[2], 0.f);
    float o3 = fmaxf(q1.y * inv + bp[3], 0.f);
    float o4 = fmaxf(q2.x * inv + bp[4], 0.f);
    float o5 = fmaxf(q2.y * inv + bp[5], 0.f);
    float o6 = fmaxf(q3.x * inv + bp[6], 0.f);
    float o7 = fmaxf(q3.y * inv + bp[7], 0.f);
    if (outp) {
        __stcs((float4*)(outp + n * 256 + l * 8),     make_float4(o0, o1, o2, o3));
        __stcs((float4*)(outp + n * 256 + l * 8 + 4), make_float4(o4, o5, o6, o7));
    } else {
        __half2 p0h = __floats2half2_rn(o0, o1);
        __half2 p1h = __floats2half2_rn(o2, o3);
        __half2 p2h = __floats2half2_rn(o4, o5);
        __half2 p3h = __floats2half2_rn(o6, o7);
        uint4 pk;
        pk.x = *(unsigned*)&p0h; pk.y = *(unsigned*)&p1h;
        pk.z = *(unsigned*)&p2h; pk.w = *(unsigned*)&p3h;
        __stcs((uint4*)(g_o2 + n * 128 + l * 4), pk);
    }

    if (reset && l == 0) {
        g_cnt[n] = 0;
        g_easum[n] = 0.0f;
        if (n < 64) g_bflag[n] = 0;
        if (n == 0) g_barrier = 0;
    }
}

// ---------------- launch ------------------------------------------------------
extern "C" void kernel_launch(void* const* d_in, const int* in_sizes, int n_in,
                              void* d_out, int out_size) {
    const float* x   = (const float*)d_in[0];
    const int*   ei  = (const int*)d_in[1];
    const float* ea  = (const float*)d_in[2];
    const float* W1  = (const float*)d_in[3];
    const float* as1 = (const float*)d_in[4];
    const float* ad1 = (const float*)d_in[5];
    const float* We1 = (const float*)d_in[6];
    const float* ae1 = (const float*)d_in[7];
    const float* b1  = (const float*)d_in[8];
    const float* W2  = (const float*)d_in[9];
    const float* as2 = (const float*)d_in[10];
    const float* ad2 = (const float*)d_in[11];
    const float* We2 = (const float*)d_in[12];
    const float* ae2 = (const float*)d_in[13];
    const float* b2  = (const float*)d_in[14];
    const float* W3  = (const float*)d_in[15];
    const float* as3 = (const float*)d_in[16];
    const float* ad3 = (const float*)d_in[17];
    const float* We3 = (const float*)d_in[18];
    const float* ae3 = (const float*)d_in[19];
    const float* b3  = (const float*)d_in[20];
    float* out = (float*)d_out;

    const int scanBlk = (NN + 1023) / 1024;        // 49
    const int attnBlk = (NN * 32 + 255) / 256;     // 6250

    // 0: layer-1 node logits + g_we + histogram
    k_front<<<NA1BLK + HISTBLK, 256>>>(x, W1, as1, ad1, We1, ae1, ei, ea);
    // 1: fused prefix scan + CSR scatter
    k_scanbuild<<<scanBlk, 1024>>>(ei, ea);
    // 2: layer-1 attention (writes g_o2 fp16)
    k_attn1<<<attnBlk, 256>>>(x, W1, b1);

    dim3 gGemm(2, (NN + 127) / 128);

    // layer 2  (3: gemm is the profiled launch)
    k_gemm_f16<<<gGemm, 256>>>(W2, NN);
    k_nodeatt<<<attnBlk + 1, 256>>>(as2, ad2, We2, ae2);
    k_attn<<<attnBlk, 256>>>(b2, nullptr, 0);

    // layer 3 -> d_out (+ reset counters for next launch)
    k_gemm_f16<<<gGemm, 256>>>(W3, NN);
    k_nodeatt<<<attnBlk + 1, 256>>>(as3, ad3, We3, ae3);
    k_attn<<<attnBlk, 256>>>(b3, out, 1);
}

// round 10
// speedup vs baseline: 1.4555x; 1.0249x over previous
#include <cuda_runtime.h>
#include <cuda_fp16.h>
#include <math.h>

// Problem constants (fixed shapes per reference)
#define NN 50000
#define EE 800000
#define HH 8
#define HC 256
#define SLOPE 0.2f

// ---------------- static device scratch (no allocations allowed) --------------
__device__ __half2 g_h2[NN * HC / 2]; // projected features (fp16, 128 half2/row)
__device__ __half2 g_o2[NN * HC / 2]; // layer output (fp16, input to next GEMM)
__device__ __half  g_Wh2[HC * HC];    // W2 in fp16
__device__ __half  g_Wh3[HC * HC];    // W3 in fp16
__device__ float g_als[NN * HH];      // per-node src attention logits
__device__ float g_ald[NN * HH];      // per-node dst attention logits
__device__ float g_we[HH];            // edge attention weight per head
__device__ int   g_rowptr[NN + 1];
__device__ int   g_cnt[NN];           // zeroed by previous launch's tail (or static init)
__device__ int   g_tmp[NN];           // build cursor (init'd by scan)
__device__ int2  g_edge[EE];          // CSR-ordered (src, edge_attr bits)
__device__ float g_easum[NN];         // sum of incoming edge attr per node
__device__ int   g_bsum[64];
__device__ int   g_bflag[64];         // scan lookback flags (reset by attn tail)
__device__ int   g_barrier;           // grid barrier for scanbuild (reset by attn tail)

// ---------------- helpers ------------------------------------------------------
__device__ __forceinline__ float lrelu(float v) {
    return (v > 0.0f) ? v : SLOPE * v;
}
__device__ __forceinline__ void mma_f16(float* c, const unsigned* a, const unsigned* b) {
    asm volatile(
        "mma.sync.aligned.m16n8k16.row.col.f32.f16.f16.f32 "
        "{%0,%1,%2,%3},{%4,%5,%6,%7},{%8,%9},{%0,%1,%2,%3};"
        : "+f"(c[0]), "+f"(c[1]), "+f"(c[2]), "+f"(c[3])
        : "r"(a[0]), "r"(a[1]), "r"(a[2]), "r"(a[3]), "r"(b[0]), "r"(b[1]));
}
__device__ __forceinline__ void ldsm4(unsigned& r0, unsigned& r1, unsigned& r2,
                                      unsigned& r3, unsigned addr) {
    asm volatile("ldmatrix.sync.aligned.m8n8.x4.shared.b16 {%0,%1,%2,%3},[%4];"
                 : "=r"(r0), "=r"(r1), "=r"(r2), "=r"(r3) : "r"(addr));
}
__device__ __forceinline__ void ldsm4t(unsigned& r0, unsigned& r1, unsigned& r2,
                                       unsigned& r3, unsigned addr) {
    asm volatile("ldmatrix.sync.aligned.m8n8.x4.trans.shared.b16 {%0,%1,%2,%3},[%4];"
                 : "=r"(r0), "=r"(r1), "=r"(r2), "=r"(r3) : "r"(addr));
}
__device__ __forceinline__ void cpasync16(unsigned dst, const void* src, int srcsz) {
    asm volatile("cp.async.ca.shared.global [%0],[%1],16,%2;"
                 :: "r"(dst), "l"(src), "r"(srcsz) : "memory");
}
// f32x2 packed math
__device__ __forceinline__ unsigned long long splat2(float x) {
    unsigned long long r;
    asm("mov.b64 %0,{%1,%1};" : "=l"(r) : "f"(x));
    return r;
}
__device__ __forceinline__ unsigned long long pack2(float x, float y) {
    unsigned long long r;
    asm("mov.b64 %0,{%1,%2};" : "=l"(r) : "f"(x), "f"(y));
    return r;
}
__device__ __forceinline__ unsigned long long fma2(unsigned long long a,
                                                   unsigned long long b,
                                                   unsigned long long c) {
    unsigned long long d;
    asm("fma.rn.f32x2 %0,%1,%2,%3;" : "=l"(d) : "l"(a), "l"(b), "l"(c));
    return d;
}
__device__ __forceinline__ float2 unpk(unsigned long long v) {
    float2 r;
    asm("mov.b64 {%0,%1},%2;" : "=f"(r.x), "=f"(r.y) : "l"(v));
    return r;
}

// ---------------- front kernel: layer-1 logits + g_we + histogram + W cvt -----
#define NA1BLK 1563
#define HISTBLK 3125
#define CVTBLK 512
__global__ void __launch_bounds__(256) k_front(
    const float* __restrict__ x, const float* __restrict__ W1,
    const float* __restrict__ as_, const float* __restrict__ ad_,
    const float* __restrict__ We, const float* __restrict__ ae,
    const int* __restrict__ ei, const float* __restrict__ ea,
    const float* __restrict__ W2, const float* __restrict__ W3) {
    int b = blockIdx.x;
    int t = threadIdx.x;
    if (b >= NA1BLK + HISTBLK) {
        int cb = b - NA1BLK - HISTBLK;          // 0..511
        int idx = (cb & 255) * 256 + t;         // 0..65535
        if (cb < 256) g_Wh2[idx] = __float2half(W2[idx]);
        else          g_Wh3[idx] = __float2half(W3[idx]);
        return;
    }
    if (b >= NA1BLK) {
        int e = (b - NA1BLK) * 256 + t;
        if (e < EE) {
            int d = ei[EE + e];
            atomicAdd(&g_cnt[d], 1);
            atomicAdd(&g_easum[d], ea[e]);
        }
        return;
    }
    __shared__ float svs[4][8], svd[4][8];
    int h = t >> 5, lane = t & 31;
    {
        float asv = as_[t], adv = ad_[t];
#pragma unroll
        for (int k = 0; k < 4; k++) {
            float w = W1[k * 256 + t];
            float s = w * asv, d = w * adv;
            for (int o = 16; o > 0; o >>= 1) {
                s += __shfl_xor_sync(0xffffffffu, s, o);
                d += __shfl_xor_sync(0xffffffffu, d, o);
            }
            if (lane == 0) { svs[k][h] = s; svd[k][h] = d; }
        }
        if (b == 0) {
            float v = We[t] * ae[t];
            for (int o = 16; o > 0; o >>= 1) v += __shfl_xor_sync(0xffffffffu, v, o);
            if (lane == 0) g_we[h] = v;
        }
    }
    __syncthreads();
    int idx = b * 256 + t;
    if (idx >= NN * 8) return;
    int n = idx >> 3, hh = idx & 7;
    float x0 = x[n * 4], x1 = x[n * 4 + 1], x2 = x[n * 4 + 2], x3 = x[n * 4 + 3];
    g_als[idx] = x0 * svs[0][hh] + x1 * svs[1][hh] + x2 * svs[2][hh] + x3 * svs[3][hh];
    g_ald[idx] = x0 * svd[0][hh] + x1 * svd[1][hh] + x2 * svd[2][hh] + x3 * svd[3][hh];
}

// ---------------- fused scan + CSR build (grid barrier; 49 blocks resident) ----
__global__ void k_scanbuild(const int* __restrict__ ei, const float* __restrict__ ea) {
    __shared__ int s[1024];
    __shared__ int s_off;
    int bid = blockIdx.x, tid = threadIdx.x;
    int i = bid * 1024 + tid;
    int v = (i < NN) ? g_cnt[i] : 0;
    s[tid] = v;
    __syncthreads();
    for (int off = 1; off < 1024; off <<= 1) {
        int t = (tid >= off) ? s[tid - off] : 0;
        __syncthreads();
        s[tid] += t;
        __syncthreads();
    }
    if (tid == 1023) {
        g_bsum[bid] = s[1023];
        __threadfence();
        atomicExch(&g_bflag[bid], 1);
    }
    if (tid < 32) {
        int sum = 0;
        for (int p = tid; p < bid; p += 32) {
            while (atomicAdd(&g_bflag[p], 0) == 0) {}
            sum += atomicAdd(&g_bsum[p], 0);
        }
        for (int o = 16; o > 0; o >>= 1) sum += __shfl_xor_sync(0xffffffffu, sum, o);
        if (tid == 0) s_off = sum;
    }
    if (bid == 0 && tid == 0) g_rowptr[NN] = EE;
    __syncthreads();
    if (i < NN) {
        int r = s[tid] - v + s_off;
        g_rowptr[i] = r;
        g_tmp[i] = r;
    }
    __threadfence();
    __syncthreads();
    if (tid == 0) {
        atomicAdd(&g_barrier, 1);
        while (atomicAdd(&g_barrier, 0) < (int)gridDim.x) {}
    }
    __syncthreads();
    int nthr = gridDim.x * 1024;
    for (int e = bid * 1024 + tid; e < EE; e += nthr) {
        int d = ei[EE + e];
        int pos = atomicAdd(&g_tmp[d], 1);
        int2 rec;
        rec.x = ei[e];
        rec.y = __float_as_int(ea[e]);
        g_edge[pos] = rec;
    }
}

// ---------------- layer-1 fused attention (group-parallel, rank-4) ------------
__global__ void __launch_bounds__(256) k_attn1(
    const float* __restrict__ x, const float* __restrict__ W1,
    const float* __restrict__ bias) {
    int warp = (blockIdx.x * blockDim.x + threadIdx.x) >> 5;
    if (warp >= NN) return;
    int n = warp;
    int l = threadIdx.x & 31;
    int g = l >> 3, h = l & 7;

    float we = g_we[h];
    float ald = g_ald[n * 8 + h];
    int start = g_rowptr[n], end = g_rowptr[n + 1];

    float m = -1e30f, psum = 0.0f;
    float4 acc = make_float4(0.f, 0.f, 0.f, 0.f);
    for (int i = start + g; i < end; i += 4) {
        int2 r = g_edge[i];
        int s = r.x;
        float ev = __int_as_float(r.y);
        float al = g_als[s * 8 + h];
        float4 xv = *(const float4*)(x + s * 4);
        float lg = lrelu(al + ald + ev * we);
        float nm = fmaxf(m, lg);
        float sc = __expf(m - nm);
        float p = __expf(lg - nm);
        psum = psum * sc + p;
        acc.x = acc.x * sc + p * xv.x;
        acc.y = acc.y * sc + p * xv.y;
        acc.z = acc.z * sc + p * xv.z;
        acc.w = acc.w * sc + p * xv.w;
        m = nm;
    }
#pragma unroll
    for (int off = 8; off <= 16; off <<= 1) {
        float mo  = __shfl_xor_sync(0xffffffffu, m, off);
        float pso = __shfl_xor_sync(0xffffffffu, psum, off);
        float ax  = __shfl_xor_sync(0xffffffffu, acc.x, off);
        float ay  = __shfl_xor_sync(0xffffffffu, acc.y, off);
        float az  = __shfl_xor_sync(0xffffffffu, acc.z, off);
        float aw  = __shfl_xor_sync(0xffffffffu, acc.w, off);
        float M = fmaxf(m, mo);
        float e1 = __expf(m - M);
        float e2 = __expf(mo - M);
        psum = psum * e1 + pso * e2;
        acc.x = acc.x * e1 + ax * e2;
        acc.y = acc.y * e1 + ay * e2;
        acc.z = acc.z * e1 + az * e2;
        acc.w = acc.w * e1 + aw * e2;
        m = M;
    }

    float inv = 1.0f / (psum + 1e-16f);
    float4 aggv = make_float4(acc.x * inv, acc.y * inv, acc.z * inv, acc.w * inv);
    int src = l >> 2;
    float a0 = __shfl_sync(0xffffffffu, aggv.x, src);
    float a1 = __shfl_sync(0xffffffffu, aggv.y, src);
    float a2 = __shfl_sync(0xffffffffu, aggv.z, src);
    float a3 = __shfl_sync(0xffffffffu, aggv.w, src);

    float o[8];
#pragma unroll
    for (int cc = 0; cc < 8; cc++) {
        int ch = l * 8 + cc;
        float v = fmaf(a0, W1[ch],
                  fmaf(a1, W1[256 + ch],
                  fmaf(a2, W1[512 + ch],
                  fmaf(a3, W1[768 + ch], bias[ch]))));
        o[cc] = fmaxf(v, 0.0f);
    }
    __half2 p0 = __floats2half2_rn(o[0], o[1]);
    __half2 p1 = __floats2half2_rn(o[2], o[3]);
    __half2 p2 = __floats2half2_rn(o[4], o[5]);
    __half2 p3 = __floats2half2_rn(o[6], o[7]);
    uint4 pk;
    pk.x = *(unsigned*)&p0; pk.y = *(unsigned*)&p1;
    pk.z = *(unsigned*)&p2; pk.w = *(unsigned*)&p3;
    __stcs((uint4*)(g_o2 + n * 128 + l * 4), pk);
}

// ---------------- node attention logits for layers 2,3 (warp per node) --------
__global__ void k_nodeatt(const float* __restrict__ as_, const float* __restrict__ ad_,
                          const float* __restrict__ We, const float* __restrict__ ae) {
    if (blockIdx.x == gridDim.x - 1) {
        int t = threadIdx.x;
        int h = t >> 5, lane = t & 31;
        float v = We[t] * ae[t];
        for (int o = 16; o > 0; o >>= 1) v += __shfl_xor_sync(0xffffffffu, v, o);
        if (lane == 0) g_we[h] = v;
        return;
    }
    int warp = (blockIdx.x * blockDim.x + threadIdx.x) >> 5;
    if (warp >= NN) return;
    int n = warp;
    int l = threadIdx.x & 31;
    uint4 hv = *(const uint4*)(g_h2 + n * 128 + l * 4);
    float f[8];
    {
        float2 c0 = __half22float2(*(__half2*)&hv.x);
        float2 c1 = __half22float2(*(__half2*)&hv.y);
        float2 c2 = __half22float2(*(__half2*)&hv.z);
        float2 c3 = __half22float2(*(__half2*)&hv.w);
        f[0] = c0.x; f[1] = c0.y; f[2] = c1.x; f[3] = c1.y;
        f[4] = c2.x; f[5] = c2.y; f[6] = c3.x; f[7] = c3.y;
    }
    const float* asp = as_ + l * 8;
    const float* adp = ad_ + l * 8;
    float s = 0.f, d = 0.f;
#pragma unroll
    for (int q = 0; q < 8; q++) {
        s = fmaf(f[q], asp[q], s);
        d = fmaf(f[q], adp[q], d);
    }
    s += __shfl_xor_sync(0xffffffffu, s, 1);
    s += __shfl_xor_sync(0xffffffffu, s, 2);
    d += __shfl_xor_sync(0xffffffffu, d, 1);
    d += __shfl_xor_sync(0xffffffffu, d, 2);
    if ((l & 3) == 0) {
        g_als[n * 8 + (l >> 2)] = s;
        g_ald[n * 8 + (l >> 2)] = d;
    }
}

// ---------------- FP16 tensor-core GEMM: g_h2 = fp16(g_o2 @ Wh) ----------------
// Block 128x128, k-chunk 32, 2-stage cp.async double buffer, one sync per chunk.
__global__ void __launch_bounds__(256, 2) k_gemm_f16(const __half* __restrict__ Wh,
                                                     int M) {
    __shared__ __half As[2][128][40];   // [m][k], 80B rows (LDSM conflict-free)
    __shared__ __half Bs[2][32][136];   // [k][n], 272B rows (LDSM conflict-free)
    const __half* A = (const __half*)g_o2;

    int tid = threadIdx.x;
    int rowBase = blockIdx.y * 128;
    int colBase = blockIdx.x * 128;
    int wid = tid >> 5, lane = tid & 31;
    int wm = wid & 3, wn = wid >> 2;            // 4x2 warp grid
    int gid = lane >> 2, tg = lane & 3;

    // staging maps: A 128x32 halves, 16 halves (2x16B) per thread
    int arow = tid >> 1, ak = (tid & 1) * 16;
    // B 32x128 halves, 16 halves (2x16B) per thread
    int brow = tid >> 3, bcol = (tid & 7) * 16;
    bool aval = (rowBase + arow) < M;
    int asz = aval ? 16 : 0;
    const __half* Ap = A + (rowBase + arow) * 256 + ak;
    const __half* Bp = Wh + brow * 256 + colBase + bcol;

    unsigned sa[2], sb[2];
#pragma unroll
    for (int f = 0; f < 2; f++) {
        sa[f] = (unsigned)__cvta_generic_to_shared(&As[f][arow][ak]);
        sb[f] = (unsigned)__cvta_generic_to_shared(&Bs[f][brow][bcol]);
    }

    float acc[2][8][4];
#pragma unroll
    for (int i = 0; i < 2; i++)
#pragma unroll
        for (int j = 0; j < 8; j++)
#pragma unroll
            for (int q = 0; q < 4; q++) acc[i][j][q] = 0.0f;

    // prologue: stage chunk 0 into buf 0
    cpasync16(sa[0],      Ap,     asz);
    cpasync16(sa[0] + 16, Ap + 8, asz);
    cpasync16(sb[0],      Bp,     16);
    cpasync16(sb[0] + 16, Bp + 8, 16);
    asm volatile("cp.async.commit_group;" ::: "memory");

#pragma unroll
    for (int it = 0; it < 8; it++) {
        int cur = it & 1;
        asm volatile("cp.async.wait_group 0;" ::: "memory");
        __syncthreads();
        if (it < 7) {
            const __half* Ap2 = Ap + (it + 1) * 32;
            const __half* Bp2 = Bp + (it + 1) * 32 * 256;
            int nxt = cur ^ 1;
            cpasync16(sa[nxt],      Ap2,     asz);
            cpasync16(sa[nxt] + 16, Ap2 + 8, asz);
            cpasync16(sb[nxt],      Bp2,     16);
            cpasync16(sb[nxt] + 16, Bp2 + 8, 16);
            asm volatile("cp.async.commit_group;" ::: "memory");
        }
        // compute from buf cur: 2 k-steps of 16
#pragma unroll
        for (int ks = 0; ks < 2; ks++) {
            int k0 = ks * 16;
            unsigned a[2][4];
#pragma unroll
            for (int i = 0; i < 2; i++) {
                int row = wm * 32 + i * 16 + (lane & 15);
                int ko = k0 + ((lane >> 4) << 3);
                unsigned ad = (unsigned)__cvta_generic_to_shared(&As[cur][row][ko]);
                ldsm4(a[i][0], a[i][1], a[i][2], a[i][3], ad);
            }
            unsigned b[8][2];
            {
                int kr = k0 + (lane & 7);
                int nb = ((lane >> 3) << 3);
                unsigned ad0 = (unsigned)__cvta_generic_to_shared(&Bs[cur][kr][wn * 64 + nb]);
                unsigned ad1 = (unsigned)__cvta_generic_to_shared(&Bs[cur][kr][wn * 64 + 32 + nb]);
                int kr2 = kr + 8;
                unsigned ad2 = (unsigned)__cvta_generic_to_shared(&Bs[cur][kr2][wn * 64 + nb]);
                unsigned ad3 = (unsigned)__cvta_generic_to_shared(&Bs[cur][kr2][wn * 64 + 32 + nb]);
                ldsm4t(b[0][0], b[1][0], b[2][0], b[3][0], ad0);
                ldsm4t(b[4][0], b[5][0], b[6][0], b[7][0], ad1);
                ldsm4t(b[0][1], b[1][1], b[2][1], b[3][1], ad2);
                ldsm4t(b[4][1], b[5][1], b[6][1], b[7][1], ad3);
            }
#pragma unroll
            for (int i = 0; i < 2; i++)
#pragma unroll
                for (int j = 0; j < 8; j++) mma_f16(acc[i][j], a[i], b[j]);
        }
    }

    // epilogue -> fp16 g_h2
#pragma unroll
    for (int i = 0; i < 2; i++) {
        int r0 = rowBase + wm * 32 + i * 16 + gid;
        int r1 = r0 + 8;
#pragma unroll
        for (int j = 0; j < 8; j++) {
            int col = colBase + wn * 64 + j * 8 + tg * 2;   // even
            if (r0 < M)
                g_h2[r0 * 128 + (col >> 1)] = __floats2half2_rn(acc[i][j][0], acc[i][j][1]);
            if (r1 < M)
                g_h2[r1 * 128 + (col >> 1)] = __floats2half2_rn(acc[i][j][2], acc[i][j][3]);
        }
    }
}

// ---------------- fused attention + aggregation (layers 2,3, self-loops) ------
__global__ void __launch_bounds__(256) k_attn(const float* __restrict__ bias,
                                              float* __restrict__ outp, int reset) {
    int warp = (blockIdx.x * blockDim.x + threadIdx.x) >> 5;
    if (warp >= NN) return;
    int n = warp;
    int l = threadIdx.x & 31;
    int head = l >> 2;

    float we = g_we[head];
    float ald = g_ald[n * 8 + head];
    int start = g_rowptr[n], end = g_rowptr[n + 1];

    float le = g_easum[n] / fmaxf((float)(end - start), 1.0f);
    float m = lrelu(g_als[n * 8 + head] + ald + le * we);
    float psum = 1.0f;
    unsigned long long acc2[4];
    {
        uint4 hv = *(const uint4*)(g_h2 + n * 128 + l * 4);
        const __half2* hp = (const __half2*)&hv;
#pragma unroll
        for (int j = 0; j < 4; j++) {
            float2 c = __half22float2(hp[j]);
            acc2[j] = pack2(c.x, c.y);
        }
    }

    int i = start;
    for (; i + 2 <= end; i += 2) {
        int2 r0 = __ldcs(&g_edge[i]), r1 = __ldcs(&g_edge[i + 1]);
        int s0 = r0.x, s1 = r1.x;
        float e0 = __int_as_float(r0.y), e1 = __int_as_float(r1.y);
        float al0 = g_als[s0 * 8 + head], al1 = g_als[s1 * 8 + head];
        uint4 v0 = *(const uint4*)(g_h2 + s0 * 128 + l * 4);
        uint4 v1 = *(const uint4*)(g_h2 + s1 * 128 + l * 4);
        float lg0 = lrelu(al0 + ald + e0 * we);
        float lg1 = lrelu(al1 + ald + e1 * we);
        float nm = fmaxf(m, fmaxf(lg0, lg1));
        float sc = __expf(m - nm);
        float p0 = __expf(lg0 - nm);
        float p1 = __expf(lg1 - nm);
        psum = psum * sc + p0 + p1;
        unsigned long long sc2 = splat2(sc), p02 = splat2(p0), p12 = splat2(p1);
        const __half2* h0 = (const __half2*)&v0;
        const __half2* h1 = (const __half2*)&v1;
#pragma unroll
        for (int j = 0; j < 4; j++) {
            float2 c0 = __half22float2(h0[j]);
            float2 c1 = __half22float2(h1[j]);
            unsigned long long w = fma2(pack2(c1.x, c1.y), p12, 0ull);
            w = fma2(pack2(c0.x, c0.y), p02, w);
            acc2[j] = fma2(acc2[j], sc2, w);
        }
        m = nm;
    }
    if (i < end) {
        int2 r0 = __ldcs(&g_edge[i]);
        int s0 = r0.x;
        float e0 = __int_as_float(r0.y);
        float lg0 = lrelu(g_als[s0 * 8 + head] + ald + e0 * we);
        uint4 v0 = *(const uint4*)(g_h2 + s0 * 128 + l * 4);
        float nm = fmaxf(m, lg0);
        float sc = __expf(m - nm);
        float p0 = __expf(lg0 - nm);
        psum = psum * sc + p0;
        unsigned long long sc2 = splat2(sc), p02 = splat2(p0);
        const __half2* h0 = (const __half2*)&v0;
#pragma unroll
        for (int j = 0; j < 4; j++) {
            float2 c0 = __half22float2(h0[j]);
            unsigned long long w = fma2(pack2(c0.x, c0.y), p02, 0ull);
            acc2[j] = fma2(acc2[j], sc2, w);
        }
    }

    float inv = 1.0f / (psum + 1e-16f);
    float2 q0 = unpk(acc2[0]), q1 = unpk(acc2[1]);
    float2 q2 = unpk(acc2[2]), q3 = unpk(acc2[3]);
    const float* bp = bias + l * 8;
    float o0 = fmaxf(q0.x * inv + bp[0], 0.f);
    float o1 = fmaxf(q0.y * inv + bp[1], 0.f);
    float o2 = fmaxf(q1.x * inv + bp[2], 0.f);
    float o3 = fmaxf(q1.y * inv + bp[3], 0.f);
    float o4 = fmaxf(q2.x * inv + bp[4], 0.f);
    float o5 = fmaxf(q2.y * inv + bp[5], 0.f);
    float o6 = fmaxf(q3.x * inv + bp[6], 0.f);
    float o7 = fmaxf(q3.y * inv + bp[7], 0.f);
    if (outp) {
        __stcs((float4*)(outp + n * 256 + l * 8),     make_float4(o0, o1, o2, o3));
        __stcs((float4*)(outp + n * 256 + l * 8 + 4), make_float4(o4, o5, o6, o7));
    } else {
        __half2 p0h = __floats2half2_rn(o0, o1);
        __half2 p1h = __floats2half2_rn(o2, o3);
        __half2 p2h = __floats2half2_rn(o4, o5);
        __half2 p3h = __floats2half2_rn(o6, o7);
        uint4 pk;
        pk.x = *(unsigned*)&p0h; pk.y = *(unsigned*)&p1h;
        pk.z = *(unsigned*)&p2h; pk.w = *(unsigned*)&p3h;
        __stcs((uint4*)(g_o2 + n * 128 + l * 4), pk);
    }

    if (reset && l == 0) {
        g_cnt[n] = 0;
        g_easum[n] = 0.0f;
        if (n < 64) g_bflag[n] = 0;
        if (n == 0) g_barrier = 0;
    }
}

// ---------------- launch ------------------------------------------------------
extern "C" void kernel_launch(void* const* d_in, const int* in_sizes, int n_in,
                              void* d_out, int out_size) {
    const float* x   = (const float*)d_in[0];
    const int*   ei  = (const int*)d_in[1];
    const float* ea  = (const float*)d_in[2];
    const float* W1  = (const float*)d_in[3];
    const float* as1 = (const float*)d_in[4];
    const float* ad1 = (const float*)d_in[5];
    const float* We1 = (const float*)d_in[6];
    const float* ae1 = (const float*)d_in[7];
    const float* b1  = (const float*)d_in[8];
    const float* W2  = (const float*)d_in[9];
    const float* as2 = (const float*)d_in[10];
    const float* ad2 = (const float*)d_in[11];
    const float* We2 = (const float*)d_in[12];
    const float* ae2 = (const float*)d_in[13];
    const float* b2  = (const float*)d_in[14];
    const float* W3  = (const float*)d_in[15];
    const float* as3 = (const float*)d_in[16];
    const float* ad3 = (const float*)d_in[17];
    const float* We3 = (const float*)d_in[18];
    const float* ae3 = (const float*)d_in[19];
    const float* b3  = (const float*)d_in[20];
    float* out = (float*)d_out;

    const int scanBlk = (NN + 1023) / 1024;        // 49
    const int attnBlk = (NN * 32 + 255) / 256;     // 6250

    __half* wh2 = nullptr;
    __half* wh3 = nullptr;
    cudaGetSymbolAddress((void**)&wh2, g_Wh2);
    cudaGetSymbolAddress((void**)&wh3, g_Wh3);

    // 0: layer-1 node logits + g_we + histogram + W fp16 conversion
    k_front<<<NA1BLK + HISTBLK + CVTBLK, 256>>>(x, W1, as1, ad1, We1, ae1, ei, ea, W2, W3);
    // 1: fused prefix scan + CSR scatter
    k_scanbuild<<<scanBlk, 1024>>>(ei, ea);
    // 2: layer-1 attention (writes g_o2 fp16)
    k_attn1<<<attnBlk, 256>>>(x, W1, b1);

    dim3 gGemm(2, (NN + 127) / 128);

    // layer 2  (3: gemm is the profiled launch)
    k_gemm_f16<<<gGemm, 256>>>(wh2, NN);
    k_nodeatt<<<attnBlk + 1, 256>>>(as2, ad2, We2, ae2);
    k_attn<<<attnBlk, 256>>>(b2, nullptr, 0);

    // layer 3 -> d_out (+ reset counters for next launch)
    k_gemm_f16<<<gGemm, 256>>>(wh3, NN);
    k_nodeatt<<<attnBlk + 1, 256>>>(as3, ad3, We3, ae3);
    k_attn<<<attnBlk, 256>>>(b3, out, 1);
}